// round 3
// baseline (speedup 1.0000x reference)
#include <cuda_runtime.h>
#include <cstdint>
#include <cstddef>

#define NN   100000
#define EE   1600000
#define DDIM 128
#define RREL 8
#define BBAS 4
#define OUTD 64

// ---------------- scratch (no cudaMalloc allowed) ----------------
__device__ float g_agg[(size_t)NN * RREL * DDIM];   // 409.6 MB
__device__ float g_cnt[NN * RREL];                  // 3.2 MB
__device__ float g_gs[(size_t)NN * DDIM];           // 51.2 MB
__device__ float g_gc[NN];                          // 0.4 MB
__device__ float g_Z[(size_t)NN * 640];             // 256 MB

// ---------------- f32x2 packed math helpers ----------------
__device__ __forceinline__ unsigned long long pk2(float x, float y) {
    unsigned long long r;
    asm("mov.b64 %0, {%1,%2};" : "=l"(r) : "f"(x), "f"(y));
    return r;
}
__device__ __forceinline__ void upk2(unsigned long long v, float& x, float& y) {
    asm("mov.b64 {%0,%1}, %2;" : "=f"(x), "=f"(y) : "l"(v));
}
__device__ __forceinline__ unsigned long long ffma2(unsigned long long a,
                                                    unsigned long long b,
                                                    unsigned long long c) {
    unsigned long long d;
    asm("fma.rn.f32x2 %0, %1, %2, %3;" : "=l"(d) : "l"(a), "l"(b), "l"(c));
    return d;
}

// ---------------- vector RED + cp.async helpers ----------------
__device__ __forceinline__ void red4(float* p, float x, float y, float z, float w) {
    asm volatile("red.global.add.v4.f32 [%0], {%1,%2,%3,%4};"
                 :: "l"(p), "f"(x), "f"(y), "f"(z), "f"(w) : "memory");
}
__device__ __forceinline__ void cp16(uint32_t dst, const void* src, int srcsz) {
    asm volatile("cp.async.ca.shared.global [%0], [%1], 16, %2;"
                 :: "r"(dst), "l"(src), "r"(srcsz));
}
__device__ __forceinline__ void cp_commit() {
    asm volatile("cp.async.commit_group;");
}
template <int N>
__device__ __forceinline__ void cp_wait() {
    asm volatile("cp.async.wait_group %0;" :: "n"(N));
}

// ---------------- edge scatter: agg (by dst,rel) + gate (by src) ----------------
__global__ void edge_kernel(const float* __restrict__ h,
                            const int* __restrict__ src,
                            const int* __restrict__ dst,
                            const int* __restrict__ et,
                            int docnt) {
    int e = blockIdx.x * 8 + (threadIdx.x >> 5);
    if (e >= EE) return;
    int lane = threadIdx.x & 31;
    int s = src[e], t = dst[e], q = et[e];

    float4 a = ((const float4*)(h + (size_t)s * DDIM))[lane];
    float4 b = ((const float4*)(h + (size_t)t * DDIM))[lane];

    float* ap = g_agg + ((size_t)t * RREL + q) * DDIM + lane * 4;
    red4(ap, a.x, a.y, a.z, a.w);

    float dx = a.x - b.x, dy = a.y - b.y, dz = a.z - b.z, dw = a.w - b.w;
    float* gp = g_gs + (size_t)s * DDIM + lane * 4;
    red4(gp, dx * dx, dy * dy, dz * dz, dw * dw);

    if (docnt && lane == 0) {
        atomicAdd(&g_cnt[t * RREL + q], 1.0f);
        atomicAdd(&g_gc[s], 1.0f);
    }
}

// ---------------- Z build (optionally zero-fills agg behind itself) ----------------
__global__ void z_kernel(const float* __restrict__ h,
                         const float* __restrict__ comp,   // [R,B]
                         float* __restrict__ Z,
                         int clear) {
    int n = blockIdx.x;
    int d = threadIdx.x;     // 0..127
    __shared__ float icnt[RREL];
    __shared__ float sc[RREL * BBAS];
    if (d < RREL * BBAS) sc[d] = comp[d];
    if (d < RREL) {
        float c = g_cnt[n * RREL + d];
        icnt[d] = 1.0f / fmaxf(c, 1.0f);
    }
    __syncthreads();

    float* ag = g_agg + (size_t)n * (RREL * DDIM);
    float acc[BBAS] = {0.f, 0.f, 0.f, 0.f};
#pragma unroll
    for (int r = 0; r < RREL; ++r) {
        float v = ag[r * DDIM + d] * icnt[r];
#pragma unroll
        for (int b = 0; b < BBAS; ++b) acc[b] += sc[r * BBAS + b] * v;
    }
    if (clear) {
#pragma unroll
        for (int r = 0; r < RREL; ++r) ag[r * DDIM + d] = 0.f;
    }
    float* zr = Z + (size_t)n * 640;
#pragma unroll
    for (int b = 0; b < BBAS; ++b) zr[b * DDIM + d] = acc[b];
    zr[512 + d] = h[(size_t)n * DDIM + d];
}

// ---------------- cp.async double-buffered fp32x2 GEMM ----------------
// tile: 64 M x NC, 256 threads, 4 rows x NCT cols per thread, BK=32 chunks
// C[M,NC] = epi( A[M,K] @ [B1 (K1 rows); B2 (K-K1 rows)] )
template <int NC, int EPI>
__global__ __launch_bounds__(256, 3)
void gemm_k(const float* __restrict__ A, int M, int K,
            const float* __restrict__ B1, int K1,
            const float* __restrict__ B2,
            const float* __restrict__ bias,
            const float* __restrict__ hprev,
            const float* __restrict__ gs,
            const float* __restrict__ gc,
            float* __restrict__ out) {
    constexpr int BK   = 32;
    constexpr int APAD = BK + 4;          // 36
    constexpr int BPAD = NC + 4;
    extern __shared__ float sm[];
    float* As[2] = {sm, sm + 64 * APAD};
    float* Bs[2] = {sm + 2 * 64 * APAD, sm + 2 * 64 * APAD + BK * BPAD};

    const int tid = threadIdx.x;
    const int tx = tid & 15;              // 16 col groups
    const int ty = tid >> 4;              // 16 row groups (4 rows each)
    const int row0 = blockIdx.x * 64;

    constexpr int NCT = NC / 16;          // 8 or 4
    constexpr int NPR = NCT / 2;          // 4 or 2

    unsigned long long acc[4][NPR];
#pragma unroll
    for (int i = 0; i < 4; ++i)
#pragma unroll
        for (int j = 0; j < NPR; ++j) acc[i][j] = 0ull;

    const int nch = K / BK;

    auto load_chunk = [&](int c, int buf) {
        const int k0 = c * BK;
        // A tile: 64 rows x 8 float4 = 512 slots, 2 per thread
#pragma unroll
        for (int u = 0; u < 2; ++u) {
            int fid = u * 256 + tid;
            int r = fid >> 3;
            int q = fid & 7;
            int grow = row0 + r;
            uint32_t dsts = (uint32_t)__cvta_generic_to_shared(As[buf] + r * APAD + q * 4);
            const float* srcp = A + (size_t)(grow < M ? grow : 0) * K + k0 + q * 4;
            cp16(dsts, srcp, grow < M ? 16 : 0);
        }
        // B tile: BK rows x NC/4 float4
        const float* Bp = (k0 < K1) ? (B1 + (size_t)k0 * NC)
                                    : (B2 + (size_t)(k0 - K1) * NC);
#pragma unroll
        for (int u = 0; u < (BK * NC / 4) / 256; ++u) {
            int fid = u * 256 + tid;
            int r = fid / (NC / 4);
            int c4 = fid % (NC / 4);
            uint32_t dsts = (uint32_t)__cvta_generic_to_shared(Bs[buf] + r * BPAD + c4 * 4);
            cp16(dsts, Bp + (size_t)r * NC + c4 * 4, 16);
        }
    };

    load_chunk(0, 0);
    cp_commit();

    for (int c = 0; c < nch; ++c) {
        const int buf = c & 1;
        if (c + 1 < nch) {
            load_chunk(c + 1, buf ^ 1);
            cp_commit();
            cp_wait<1>();
        } else {
            cp_wait<0>();
        }
        __syncthreads();

        const float* Ab = As[buf];
        const float* Bb = Bs[buf];
#pragma unroll
        for (int kk0 = 0; kk0 < BK; kk0 += 4) {
            float4 av[4];
#pragma unroll
            for (int i = 0; i < 4; ++i)
                av[i] = *(const float4*)(Ab + (ty * 4 + i) * APAD + kk0);
#pragma unroll
            for (int kk = 0; kk < 4; ++kk) {
                unsigned long long bp[NPR];
                const float* brow = Bb + (kk0 + kk) * BPAD + tx * NCT;
#pragma unroll
                for (int j = 0; j < NPR; ++j)
                    bp[j] = *(const unsigned long long*)(brow + 2 * j);
#pragma unroll
                for (int i = 0; i < 4; ++i) {
                    float a = (kk == 0) ? av[i].x : (kk == 1) ? av[i].y
                             : (kk == 2) ? av[i].z : av[i].w;
                    unsigned long long a2 = pk2(a, a);
#pragma unroll
                    for (int j = 0; j < NPR; ++j) acc[i][j] = ffma2(a2, bp[j], acc[i][j]);
                }
            }
        }
        __syncthreads();
    }

    // epilogue
#pragma unroll
    for (int i = 0; i < 4; ++i) {
        int row = row0 + ty * 4 + i;
        if (row >= M) break;
        float cv[NCT];
#pragma unroll
        for (int j = 0; j < NPR; ++j) upk2(acc[i][j], cv[2 * j], cv[2 * j + 1]);
        const int fbase = tx * NCT;
        if (EPI == 0) {
#pragma unroll
            for (int j = 0; j < NCT; ++j) cv[j] = fmaxf(cv[j] + bias[fbase + j], 0.f);
        } else if (EPI == 1) {
            float ig = 1.0f / fmaxf(gc[row], 1.0f);
#pragma unroll
            for (int j = 0; j < NCT; ++j) {
                int f = fbase + j;
                float hn = fmaxf(cv[j] + bias[f], 0.f);
                float hp = hprev[(size_t)row * DDIM + f];
                float tau = tanhf(gs[(size_t)row * DDIM + f] * ig);
                cv[j] = hp + tau * (hn - hp);
            }
        } else {
#pragma unroll
            for (int j = 0; j < NCT; ++j) cv[j] += bias[fbase + j];
        }
#pragma unroll
        for (int j4 = 0; j4 < NCT; j4 += 4) {
            *(float4*)(out + (size_t)row * NC + fbase + j4) =
                make_float4(cv[j4], cv[j4 + 1], cv[j4 + 2], cv[j4 + 3]);
        }
    }
}

// ---------------- launch ----------------
extern "C" void kernel_launch(void* const* d_in, const int* in_sizes, int n_in,
                              void* d_out, int out_size) {
    (void)in_sizes; (void)n_in; (void)out_size;
    const float* x      = (const float*)d_in[0];
    const int*   src    = (const int*)d_in[1];
    const int*   dst    = (const int*)d_in[2];
    const int*   et     = (const int*)d_in[3];
    const float* projW  = (const float*)d_in[4];
    const float* projb  = (const float*)d_in[5];
    const float* basis1 = (const float*)d_in[6];
    const float* comp1  = (const float*)d_in[7];
    const float* root1  = (const float*)d_in[8];
    const float* bias1  = (const float*)d_in[9];
    const float* basis2 = (const float*)d_in[10];
    const float* comp2  = (const float*)d_in[11];
    const float* root2  = (const float*)d_in[12];
    const float* bias2  = (const float*)d_in[13];
    const float* outW   = (const float*)d_in[14];
    const float* outb   = (const float*)d_in[15];

    float* o  = (float*)d_out;
    float* L0 = o + (size_t)NN * OUTD;        // latents[0]
    float* L1 = L0 + (size_t)NN * DDIM;       // latents[1]
    float* L2 = L1 + (size_t)NN * DDIM;       // latents[2]

    float *agg, *cnt, *gsv, *gcv, *Z;
    cudaGetSymbolAddress((void**)&agg, g_agg);
    cudaGetSymbolAddress((void**)&cnt, g_cnt);
    cudaGetSymbolAddress((void**)&gsv, g_gs);
    cudaGetSymbolAddress((void**)&gcv, g_gc);
    cudaGetSymbolAddress((void**)&Z,   g_Z);

    const int SMEM128 = (2 * 64 * 36 + 2 * 32 * 132) * 4;   // 52224
    const int SMEM64  = (2 * 64 * 36 + 2 * 32 * 68) * 4;    // 35840
    cudaFuncSetAttribute(gemm_k<128, 0>, cudaFuncAttributeMaxDynamicSharedMemorySize, SMEM128);
    cudaFuncSetAttribute(gemm_k<128, 1>, cudaFuncAttributeMaxDynamicSharedMemorySize, SMEM128);
    cudaFuncSetAttribute(gemm_k<64, 2>,  cudaFuncAttributeMaxDynamicSharedMemorySize, SMEM64);

    const int gblocks = (NN + 63) / 64;   // 1563

    // zero all scratch once (cnt/gc are layer-invariant)
    cudaMemsetAsync(agg, 0, (size_t)NN * RREL * DDIM * sizeof(float));
    cudaMemsetAsync(cnt, 0, (size_t)NN * RREL * sizeof(float));
    cudaMemsetAsync(gsv, 0, (size_t)NN * DDIM * sizeof(float));
    cudaMemsetAsync(gcv, 0, (size_t)NN * sizeof(float));

    // input projection: h0 = relu(x @ projW + projb)
    gemm_k<128, 0><<<gblocks, 256, SMEM128>>>(x, NN, 128, projW, 128, nullptr,
                                              projb, nullptr, nullptr, nullptr, L0);

    // ---------------- layer 1 ----------------
    edge_kernel<<<EE / 8, 256>>>(L0, src, dst, et, 1);
    z_kernel<<<NN, 128>>>(L0, comp1, Z, 1);   // clears agg behind itself
    gemm_k<128, 1><<<gblocks, 256, SMEM128>>>(Z, NN, 640, basis1, 512, root1,
                                              bias1, L0, gsv, gcv, L1);

    // ---------------- layer 2 ----------------
    cudaMemsetAsync(gsv, 0, (size_t)NN * DDIM * sizeof(float));
    edge_kernel<<<EE / 8, 256>>>(L1, src, dst, et, 0);
    z_kernel<<<NN, 128>>>(L1, comp2, Z, 0);
    gemm_k<128, 1><<<gblocks, 256, SMEM128>>>(Z, NN, 640, basis2, 512, root2,
                                              bias2, L1, gsv, gcv, L2);

    // final: out = h2 @ outW + outb
    gemm_k<64, 2><<<gblocks, 256, SMEM64>>>(L2, NN, 128, outW, 128, nullptr,
                                            outb, nullptr, nullptr, nullptr, o);
}

// round 4
// speedup vs baseline: 1.6340x; 1.6340x over previous
#include <cuda_runtime.h>
#include <cstdint>
#include <cstddef>

#define NN   100000
#define EE   1600000
#define DDIM 128
#define RREL 8
#define BBAS 4
#define OUTD 64

// ---------------- scratch (no cudaMalloc allowed) ----------------
__device__ float g_agg[(size_t)NN * RREL * DDIM];   // 409.6 MB
__device__ float g_cnt[NN * RREL];                  // 3.2 MB
__device__ float g_gs[(size_t)NN * DDIM];           // 51.2 MB
__device__ float g_gc[NN];                          // 0.4 MB
__device__ float g_Z[(size_t)NN * 640];             // 256 MB

// ---------------- f32x2 packed math helpers ----------------
__device__ __forceinline__ unsigned long long pk2(float x, float y) {
    unsigned long long r;
    asm("mov.b64 %0, {%1,%2};" : "=l"(r) : "f"(x), "f"(y));
    return r;
}
__device__ __forceinline__ void upk2(unsigned long long v, float& x, float& y) {
    asm("mov.b64 {%0,%1}, %2;" : "=f"(x), "=f"(y) : "l"(v));
}
__device__ __forceinline__ unsigned long long ffma2(unsigned long long a,
                                                    unsigned long long b,
                                                    unsigned long long c) {
    unsigned long long d;
    asm("fma.rn.f32x2 %0, %1, %2, %3;" : "=l"(d) : "l"(a), "l"(b), "l"(c));
    return d;
}

// ---------------- vector RED ----------------
__device__ __forceinline__ void red4(float* p, float x, float y, float z, float w) {
    asm volatile("red.global.add.v4.f32 [%0], {%1,%2,%3,%4};"
                 :: "l"(p), "f"(x), "f"(y), "f"(z), "f"(w) : "memory");
}

// ---------------- edge scatter: agg (by dst,rel) + gate (by src) ----------------
__global__ void edge_kernel(const float* __restrict__ h,
                            const int* __restrict__ src,
                            const int* __restrict__ dst,
                            const int* __restrict__ et,
                            int docnt) {
    int e = blockIdx.x * 8 + (threadIdx.x >> 5);
    if (e >= EE) return;
    int lane = threadIdx.x & 31;
    int s = src[e], t = dst[e], q = et[e];

    float4 a = ((const float4*)(h + (size_t)s * DDIM))[lane];
    float4 b = ((const float4*)(h + (size_t)t * DDIM))[lane];

    float* ap = g_agg + ((size_t)t * RREL + q) * DDIM + lane * 4;
    red4(ap, a.x, a.y, a.z, a.w);

    float dx = a.x - b.x, dy = a.y - b.y, dz = a.z - b.z, dw = a.w - b.w;
    float* gp = g_gs + (size_t)s * DDIM + lane * 4;
    red4(gp, dx * dx, dy * dy, dz * dz, dw * dw);

    if (docnt && lane == 0) {
        atomicAdd(&g_cnt[t * RREL + q], 1.0f);
        atomicAdd(&g_gc[s], 1.0f);
    }
}

// ---------------- Z build (optionally zero-fills agg behind itself) ----------------
__global__ void z_kernel(const float* __restrict__ h,
                         const float* __restrict__ comp,   // [R,B]
                         float* __restrict__ Z,
                         int clear) {
    int n = blockIdx.x;
    int d = threadIdx.x;     // 0..127
    __shared__ float icnt[RREL];
    __shared__ float sc[RREL * BBAS];
    if (d < RREL * BBAS) sc[d] = comp[d];
    if (d < RREL) {
        float c = g_cnt[n * RREL + d];
        icnt[d] = 1.0f / fmaxf(c, 1.0f);
    }
    __syncthreads();

    float* ag = g_agg + (size_t)n * (RREL * DDIM);
    float acc[BBAS] = {0.f, 0.f, 0.f, 0.f};
#pragma unroll
    for (int r = 0; r < RREL; ++r) {
        float v = ag[r * DDIM + d] * icnt[r];
#pragma unroll
        for (int b = 0; b < BBAS; ++b) acc[b] += sc[r * BBAS + b] * v;
    }
    if (clear) {
#pragma unroll
        for (int r = 0; r < RREL; ++r) ag[r * DDIM + d] = 0.f;
    }
    float* zr = Z + (size_t)n * 640;
#pragma unroll
    for (int b = 0; b < BBAS; ++b) zr[b * DDIM + d] = acc[b];
    zr[512 + d] = h[(size_t)n * DDIM + d];
}

// ---------------- single-buffer fp32x2 GEMM, conflict-free smem ----------------
// tile: 64 M x NC, 128 threads. Thread (tx,ty): rows ty*8..+7,
// columns as NPR float2 pairs at  tx*2 + j*32  (bank-conflict-free).
// C[M,NC] = epi( A[M,K] @ [B1 (K1 rows); B2 (K-K1 rows)] )
// EPI 0: relu(acc+bias)  EPI 1: gated blend  EPI 2: acc+bias
template <int NC, int EPI>
__global__ __launch_bounds__(128)
void gemm_k(const float* __restrict__ A, int M, int K,
            const float* __restrict__ B1, int K1,
            const float* __restrict__ B2,
            const float* __restrict__ bias,
            const float* __restrict__ hprev,
            const float* __restrict__ gs,
            const float* __restrict__ gc,
            float* __restrict__ out) {
    constexpr int APAD = 68;              // A row stride (floats), row-major [64][APAD]
    constexpr int BPAD = NC + 4;          // B row stride (k-major) [64][BPAD]
    extern __shared__ float sm[];
    float* As = sm;
    float* Bs = sm + 64 * APAD;

    const int tid = threadIdx.x;
    const int tx = tid & 15;              // 16 col groups
    const int ty = tid >> 4;              // 8 row groups (8 rows each)
    const int row0 = blockIdx.x * 64;

    constexpr int NCT = NC / 16;          // 8 or 4 cols per thread
    constexpr int NPR = NCT / 2;          // float2 pairs (4 or 2), pair j at tx*2+j*32

    unsigned long long acc[8][NPR];
#pragma unroll
    for (int i = 0; i < 8; ++i)
#pragma unroll
        for (int j = 0; j < NPR; ++j) acc[i][j] = 0ull;

    const int nch = K >> 6;
    for (int c = 0; c < nch; ++c) {
        const int k0 = c << 6;
        // stage A row-major: 64 rows x 16 float4 = 1024 slots, 8 per thread
#pragma unroll
        for (int u = 0; u < 8; ++u) {
            int fid = u * 128 + tid;
            int r = fid >> 4;
            int q = fid & 15;
            int grow = row0 + r;
            float4 v = make_float4(0.f, 0.f, 0.f, 0.f);
            if (grow < M) v = *(const float4*)(A + (size_t)grow * K + k0 + q * 4);
            *(float4*)(As + r * APAD + q * 4) = v;
        }
        // stage B: 64 k-rows x NC/4 float4
        const float* Bp = (k0 < K1) ? (B1 + (size_t)k0 * NC)
                                    : (B2 + (size_t)(k0 - K1) * NC);
#pragma unroll
        for (int u = 0; u < (64 * NC / 4) / 128; ++u) {
            int fid = u * 128 + tid;
            int r = fid / (NC / 4);
            int c4 = fid % (NC / 4);
            *(float4*)(Bs + r * BPAD + c4 * 4) =
                *(const float4*)(Bp + (size_t)r * NC + c4 * 4);
        }
        __syncthreads();

#pragma unroll
        for (int kk0 = 0; kk0 < 64; kk0 += 4) {
            float4 av[8];
#pragma unroll
            for (int i = 0; i < 8; ++i)
                av[i] = *(const float4*)(As + (ty * 8 + i) * APAD + kk0);
#pragma unroll
            for (int kk = 0; kk < 4; ++kk) {
                unsigned long long bp[NPR];
                const float* brow = Bs + (kk0 + kk) * BPAD + tx * 2;
#pragma unroll
                for (int j = 0; j < NPR; ++j)
                    bp[j] = *(const unsigned long long*)(brow + j * 32);
#pragma unroll
                for (int i = 0; i < 8; ++i) {
                    float a = (kk == 0) ? av[i].x : (kk == 1) ? av[i].y
                             : (kk == 2) ? av[i].z : av[i].w;
                    unsigned long long a2 = pk2(a, a);
#pragma unroll
                    for (int j = 0; j < NPR; ++j) acc[i][j] = ffma2(a2, bp[j], acc[i][j]);
                }
            }
        }
        __syncthreads();
    }

    // epilogue — pair j covers columns {tx*2 + j*32, tx*2 + j*32 + 1}
#pragma unroll
    for (int i = 0; i < 8; ++i) {
        int row = row0 + ty * 8 + i;
        if (row >= M) break;
        float ig;
        if (EPI == 1) ig = 1.0f / fmaxf(gc[row], 1.0f);
#pragma unroll
        for (int j = 0; j < NPR; ++j) {
            float c0, c1;
            upk2(acc[i][j], c0, c1);
            int f = tx * 2 + j * 32;
            if (EPI == 0) {
                c0 = fmaxf(c0 + bias[f], 0.f);
                c1 = fmaxf(c1 + bias[f + 1], 0.f);
            } else if (EPI == 1) {
                float hn0 = fmaxf(c0 + bias[f], 0.f);
                float hn1 = fmaxf(c1 + bias[f + 1], 0.f);
                float hp0 = hprev[(size_t)row * DDIM + f];
                float hp1 = hprev[(size_t)row * DDIM + f + 1];
                float t0 = tanhf(gs[(size_t)row * DDIM + f] * ig);
                float t1 = tanhf(gs[(size_t)row * DDIM + f + 1] * ig);
                c0 = hp0 + t0 * (hn0 - hp0);
                c1 = hp1 + t1 * (hn1 - hp1);
            } else {
                c0 += bias[f];
                c1 += bias[f + 1];
            }
            *(float2*)(out + (size_t)row * NC + f) = make_float2(c0, c1);
        }
    }
}

// ---------------- launch ----------------
extern "C" void kernel_launch(void* const* d_in, const int* in_sizes, int n_in,
                              void* d_out, int out_size) {
    (void)in_sizes; (void)n_in; (void)out_size;
    const float* x      = (const float*)d_in[0];
    const int*   src    = (const int*)d_in[1];
    const int*   dst    = (const int*)d_in[2];
    const int*   et     = (const int*)d_in[3];
    const float* projW  = (const float*)d_in[4];
    const float* projb  = (const float*)d_in[5];
    const float* basis1 = (const float*)d_in[6];
    const float* comp1  = (const float*)d_in[7];
    const float* root1  = (const float*)d_in[8];
    const float* bias1  = (const float*)d_in[9];
    const float* basis2 = (const float*)d_in[10];
    const float* comp2  = (const float*)d_in[11];
    const float* root2  = (const float*)d_in[12];
    const float* bias2  = (const float*)d_in[13];
    const float* outW   = (const float*)d_in[14];
    const float* outb   = (const float*)d_in[15];

    float* o  = (float*)d_out;
    float* L0 = o + (size_t)NN * OUTD;        // latents[0]
    float* L1 = L0 + (size_t)NN * DDIM;       // latents[1]
    float* L2 = L1 + (size_t)NN * DDIM;       // latents[2]

    float *agg, *cnt, *gsv, *gcv, *Z;
    cudaGetSymbolAddress((void**)&agg, g_agg);
    cudaGetSymbolAddress((void**)&cnt, g_cnt);
    cudaGetSymbolAddress((void**)&gsv, g_gs);
    cudaGetSymbolAddress((void**)&gcv, g_gc);
    cudaGetSymbolAddress((void**)&Z,   g_Z);

    const int SMEM128 = (64 * 68 + 64 * 132) * 4;   // 51200
    const int SMEM64  = (64 * 68 + 64 * 68) * 4;    // 34816
    cudaFuncSetAttribute(gemm_k<128, 0>, cudaFuncAttributeMaxDynamicSharedMemorySize, SMEM128);
    cudaFuncSetAttribute(gemm_k<128, 1>, cudaFuncAttributeMaxDynamicSharedMemorySize, SMEM128);
    cudaFuncSetAttribute(gemm_k<64, 2>,  cudaFuncAttributeMaxDynamicSharedMemorySize, SMEM64);

    const int gblocks = (NN + 63) / 64;   // 1563

    // zero all scratch once (cnt/gc are layer-invariant; agg re-cleared by z_kernel)
    cudaMemsetAsync(agg, 0, (size_t)NN * RREL * DDIM * sizeof(float));
    cudaMemsetAsync(cnt, 0, (size_t)NN * RREL * sizeof(float));
    cudaMemsetAsync(gsv, 0, (size_t)NN * DDIM * sizeof(float));
    cudaMemsetAsync(gcv, 0, (size_t)NN * sizeof(float));

    // input projection: h0 = relu(x @ projW + projb)
    gemm_k<128, 0><<<gblocks, 128, SMEM128>>>(x, NN, 128, projW, 128, nullptr,
                                              projb, nullptr, nullptr, nullptr, L0);

    // ---------------- layer 1 ----------------
    edge_kernel<<<EE / 8, 256>>>(L0, src, dst, et, 1);
    z_kernel<<<NN, 128>>>(L0, comp1, Z, 1);   // clears agg behind itself
    gemm_k<128, 1><<<gblocks, 128, SMEM128>>>(Z, NN, 640, basis1, 512, root1,
                                              bias1, L0, gsv, gcv, L1);

    // ---------------- layer 2 ----------------
    cudaMemsetAsync(gsv, 0, (size_t)NN * DDIM * sizeof(float));
    edge_kernel<<<EE / 8, 256>>>(L1, src, dst, et, 0);
    z_kernel<<<NN, 128>>>(L1, comp2, Z, 0);
    gemm_k<128, 1><<<gblocks, 128, SMEM128>>>(Z, NN, 640, basis2, 512, root2,
                                              bias2, L1, gsv, gcv, L2);

    // final: out = h2 @ outW + outb
    gemm_k<64, 2><<<gblocks, 128, SMEM64>>>(L2, NN, 128, outW, 128, nullptr,
                                            outb, nullptr, nullptr, nullptr, o);
}

// round 5
// speedup vs baseline: 2.3685x; 1.4495x over previous
#include <cuda_runtime.h>
#include <cstdint>
#include <cstddef>

#define NN   100000
#define EE   1600000
#define DDIM 128
#define RREL 8
#define BBAS 4
#define OUTD 64

// ---------------- scratch (no cudaMalloc allowed) ----------------
__device__ float g_Z[(size_t)NN * 512];     // contracted aggregate [N, B*D] = 205 MB
__device__ float g_tau[(size_t)NN * DDIM];  // gate tau [N, D]
__device__ int   g_sd[EE];                  // edges sorted by dst: src | (q<<20)
__device__ int   g_ss[EE];                  // edges sorted by src: dst
__device__ int   g_offd[NN + 1];
__device__ int   g_offs[NN + 1];
__device__ int   g_curd[NN];
__device__ int   g_curs[NN];

// ---------------- f32x2 packed math helpers ----------------
__device__ __forceinline__ unsigned long long pk2(float x, float y) {
    unsigned long long r;
    asm("mov.b64 %0, {%1,%2};" : "=l"(r) : "f"(x), "f"(y));
    return r;
}
__device__ __forceinline__ void upk2(unsigned long long v, float& x, float& y) {
    asm("mov.b64 {%0,%1}, %2;" : "=f"(x), "=f"(y) : "l"(v));
}
__device__ __forceinline__ unsigned long long ffma2(unsigned long long a,
                                                    unsigned long long b,
                                                    unsigned long long c) {
    unsigned long long d;
    asm("fma.rn.f32x2 %0, %1, %2, %3;" : "=l"(d) : "l"(a), "l"(b), "l"(c));
    return d;
}

// ---------------- sorting: histogram / scan / scatter ----------------
__global__ void hist_k(const int* __restrict__ src, const int* __restrict__ dst,
                       int* __restrict__ hs, int* __restrict__ hd) {
    int e = blockIdx.x * 256 + threadIdx.x;
    if (e < EE) {
        atomicAdd(&hd[dst[e]], 1);
        atomicAdd(&hs[src[e]], 1);
    }
}

// one block per histogram: exclusive scan with carry, off[n] = total
__global__ void scan_k(const int* __restrict__ h0, int* __restrict__ o0,
                       const int* __restrict__ h1, int* __restrict__ o1, int n) {
    const int* hist = (blockIdx.x == 0) ? h0 : h1;
    int* off        = (blockIdx.x == 0) ? o0 : o1;
    __shared__ int buf[2][1024];
    __shared__ int carry;
    int t = threadIdx.x;
    if (t == 0) carry = 0;
    __syncthreads();
    for (int base = 0; base < n; base += 1024) {
        int v = (base + t < n) ? hist[base + t] : 0;
        buf[0][t] = v;
        __syncthreads();
        int pi = 0;
#pragma unroll
        for (int ofs = 1; ofs < 1024; ofs <<= 1) {
            int x = buf[pi][t];
            if (t >= ofs) x += buf[pi][t - ofs];
            buf[pi ^ 1][t] = x;
            pi ^= 1;
            __syncthreads();
        }
        int incl = buf[pi][t];
        if (base + t < n) off[base + t] = carry + incl - v;
        __syncthreads();
        if (t == 1023) carry += incl;
        __syncthreads();
    }
    if (t == 0) off[n] = carry;
}

__global__ void scatter_k(const int* __restrict__ src, const int* __restrict__ dst,
                          const int* __restrict__ et,
                          int* __restrict__ curd, int* __restrict__ curs,
                          int* __restrict__ sd, int* __restrict__ ss) {
    int e = blockIdx.x * 256 + threadIdx.x;
    if (e < EE) {
        int s = src[e], t = dst[e], q = et[e];
        int p = atomicAdd(&curd[t], 1);
        sd[p] = s | (q << 20);
        int p2 = atomicAdd(&curs[s], 1);
        ss[p2] = t;
    }
}

// ---------------- passA: per-dst segmented sum + comp contraction -> Z ----------------
__global__ __launch_bounds__(128)
void passA_k(const float* __restrict__ h, const float* __restrict__ comp,
             const int* __restrict__ offd, const int* __restrict__ sd,
             float* __restrict__ Z) {
    int t = blockIdx.x;
    int d = threadIdx.x;
    __shared__ float sacc[RREL * DDIM];
    __shared__ int   scnt[RREL];
    __shared__ float scomp[RREL * BBAS];
    __shared__ int   sed[128];
#pragma unroll
    for (int q = 0; q < RREL; ++q) sacc[q * DDIM + d] = 0.f;
    if (d < RREL) scnt[d] = 0;
    if (d < RREL * BBAS) scomp[d] = comp[d];
    __syncthreads();

    int e0 = offd[t], e1 = offd[t + 1];
    for (int base = e0; base < e1; base += 128) {
        int m = min(128, e1 - base);
        if (d < m) sed[d] = sd[base + d];
        __syncthreads();
        for (int i = 0; i < m; ++i) {
            int v = sed[i];
            int s = v & 0xFFFFF;
            int q = v >> 20;
            float hv = h[(size_t)s * DDIM + d];
            sacc[q * DDIM + d] += hv;
            if (d == 0) scnt[q]++;
        }
        __syncthreads();
    }

    float w[RREL];
#pragma unroll
    for (int q = 0; q < RREL; ++q)
        w[q] = 1.0f / fmaxf((float)scnt[q], 1.0f);

    float* zr = Z + (size_t)t * 512;
#pragma unroll
    for (int b = 0; b < BBAS; ++b) {
        float o = 0.f;
#pragma unroll
        for (int q = 0; q < RREL; ++q)
            o += scomp[q * BBAS + b] * w[q] * sacc[q * DDIM + d];
        zr[b * DDIM + d] = o;
    }
}

// ---------------- passB: per-src gate tau = tanh(mean |h_s - h_d|^2) ----------------
__global__ __launch_bounds__(128)
void passB_k(const float* __restrict__ h, const int* __restrict__ offs,
             const int* __restrict__ ss, float* __restrict__ tau) {
    int s = blockIdx.x;
    int d = threadIdx.x;
    int e0 = offs[s], e1 = offs[s + 1];
    float hs = h[(size_t)s * DDIM + d];
    float a0 = 0.f, a1 = 0.f, a2 = 0.f, a3 = 0.f;
    __shared__ int sed[128];
    for (int base = e0; base < e1; base += 128) {
        int m = min(128, e1 - base);
        if (d < m) sed[d] = ss[base + d];
        __syncthreads();
        int i = 0;
        for (; i + 3 < m; i += 4) {
            float v0 = h[(size_t)sed[i + 0] * DDIM + d];
            float v1 = h[(size_t)sed[i + 1] * DDIM + d];
            float v2 = h[(size_t)sed[i + 2] * DDIM + d];
            float v3 = h[(size_t)sed[i + 3] * DDIM + d];
            float d0 = hs - v0, d1 = hs - v1, d2 = hs - v2, d3 = hs - v3;
            a0 += d0 * d0; a1 += d1 * d1; a2 += d2 * d2; a3 += d3 * d3;
        }
        for (; i < m; ++i) {
            float v = h[(size_t)sed[i] * DDIM + d];
            float df = hs - v;
            a0 += df * df;
        }
        __syncthreads();
    }
    float acc = (a0 + a1) + (a2 + a3);
    float ig = 1.0f / fmaxf((float)(e1 - e0), 1.0f);
    tau[(size_t)s * DDIM + d] = tanhf(acc * ig);
}

// ---------------- single-buffer fp32x2 GEMM, conflict-free smem ----------------
// A split: cols [0,K1A) from A1 (stride lda1), cols [K1A,K) from A2 (stride lda2)
// B split: rows [0,K1) from B1, rest from B2 (both row-major, NC cols)
// EPI 0: relu(acc+bias)  EPI 1: hp + tau*(relu(acc+bias)-hp)  EPI 2: acc+bias
template <int NC, int EPI>
__global__ __launch_bounds__(128)
void gemm_k(const float* __restrict__ A1, int lda1, int K1A,
            const float* __restrict__ A2, int lda2,
            int M, int K,
            const float* __restrict__ B1, int K1,
            const float* __restrict__ B2,
            const float* __restrict__ bias,
            const float* __restrict__ hprev,
            const float* __restrict__ tau,
            float* __restrict__ out) {
    constexpr int APAD = 68;
    constexpr int BPAD = NC + 4;
    extern __shared__ float sm[];
    float* As = sm;
    float* Bs = sm + 64 * APAD;

    const int tid = threadIdx.x;
    const int tx = tid & 15;
    const int ty = tid >> 4;
    const int row0 = blockIdx.x * 64;

    constexpr int NCT = NC / 16;
    constexpr int NPR = NCT / 2;

    unsigned long long acc[8][NPR];
#pragma unroll
    for (int i = 0; i < 8; ++i)
#pragma unroll
        for (int j = 0; j < NPR; ++j) acc[i][j] = 0ull;

    const int nch = K >> 6;
    for (int c = 0; c < nch; ++c) {
        const int k0 = c << 6;
        const float* Ap; int lda;
        if (k0 < K1A) { Ap = A1 + k0; lda = lda1; }
        else          { Ap = A2 + (k0 - K1A); lda = lda2; }
        // stage A row-major: 64 rows x 16 float4 = 1024 slots, 8 per thread
#pragma unroll
        for (int u = 0; u < 8; ++u) {
            int fid = u * 128 + tid;
            int r = fid >> 4;
            int q = fid & 15;
            int grow = row0 + r;
            float4 v = make_float4(0.f, 0.f, 0.f, 0.f);
            if (grow < M) v = *(const float4*)(Ap + (size_t)grow * lda + q * 4);
            *(float4*)(As + r * APAD + q * 4) = v;
        }
        // stage B
        const float* Bp = (k0 < K1) ? (B1 + (size_t)k0 * NC)
                                    : (B2 + (size_t)(k0 - K1) * NC);
#pragma unroll
        for (int u = 0; u < (64 * NC / 4) / 128; ++u) {
            int fid = u * 128 + tid;
            int r = fid / (NC / 4);
            int c4 = fid % (NC / 4);
            *(float4*)(Bs + r * BPAD + c4 * 4) =
                *(const float4*)(Bp + (size_t)r * NC + c4 * 4);
        }
        __syncthreads();

#pragma unroll
        for (int kk0 = 0; kk0 < 64; kk0 += 4) {
            float4 av[8];
#pragma unroll
            for (int i = 0; i < 8; ++i)
                av[i] = *(const float4*)(As + (ty * 8 + i) * APAD + kk0);
#pragma unroll
            for (int kk = 0; kk < 4; ++kk) {
                unsigned long long bp[NPR];
                const float* brow = Bs + (kk0 + kk) * BPAD + tx * 2;
#pragma unroll
                for (int j = 0; j < NPR; ++j)
                    bp[j] = *(const unsigned long long*)(brow + j * 32);
#pragma unroll
                for (int i = 0; i < 8; ++i) {
                    float a = (kk == 0) ? av[i].x : (kk == 1) ? av[i].y
                             : (kk == 2) ? av[i].z : av[i].w;
                    unsigned long long a2 = pk2(a, a);
#pragma unroll
                    for (int j = 0; j < NPR; ++j) acc[i][j] = ffma2(a2, bp[j], acc[i][j]);
                }
            }
        }
        __syncthreads();
    }

    // epilogue — pair j covers columns {tx*2 + j*32, +1}
#pragma unroll
    for (int i = 0; i < 8; ++i) {
        int row = row0 + ty * 8 + i;
        if (row >= M) break;
#pragma unroll
        for (int j = 0; j < NPR; ++j) {
            float c0, c1;
            upk2(acc[i][j], c0, c1);
            int f = tx * 2 + j * 32;
            if (EPI == 0) {
                c0 = fmaxf(c0 + bias[f], 0.f);
                c1 = fmaxf(c1 + bias[f + 1], 0.f);
            } else if (EPI == 1) {
                float hn0 = fmaxf(c0 + bias[f], 0.f);
                float hn1 = fmaxf(c1 + bias[f + 1], 0.f);
                float hp0 = hprev[(size_t)row * DDIM + f];
                float hp1 = hprev[(size_t)row * DDIM + f + 1];
                float t0 = tau[(size_t)row * DDIM + f];
                float t1 = tau[(size_t)row * DDIM + f + 1];
                c0 = hp0 + t0 * (hn0 - hp0);
                c1 = hp1 + t1 * (hn1 - hp1);
            } else {
                c0 += bias[f];
                c1 += bias[f + 1];
            }
            *(float2*)(out + (size_t)row * NC + f) = make_float2(c0, c1);
        }
    }
}

// ---------------- launch ----------------
extern "C" void kernel_launch(void* const* d_in, const int* in_sizes, int n_in,
                              void* d_out, int out_size) {
    (void)in_sizes; (void)n_in; (void)out_size;
    const float* x      = (const float*)d_in[0];
    const int*   src    = (const int*)d_in[1];
    const int*   dst    = (const int*)d_in[2];
    const int*   et     = (const int*)d_in[3];
    const float* projW  = (const float*)d_in[4];
    const float* projb  = (const float*)d_in[5];
    const float* basis1 = (const float*)d_in[6];
    const float* comp1  = (const float*)d_in[7];
    const float* root1  = (const float*)d_in[8];
    const float* bias1  = (const float*)d_in[9];
    const float* basis2 = (const float*)d_in[10];
    const float* comp2  = (const float*)d_in[11];
    const float* root2  = (const float*)d_in[12];
    const float* bias2  = (const float*)d_in[13];
    const float* outW   = (const float*)d_in[14];
    const float* outb   = (const float*)d_in[15];

    float* o  = (float*)d_out;
    float* L0 = o + (size_t)NN * OUTD;        // latents[0]
    float* L1 = L0 + (size_t)NN * DDIM;       // latents[1]
    float* L2 = L1 + (size_t)NN * DDIM;       // latents[2]

    float *Z, *tau;
    int *sd, *ss, *offd, *offs, *curd, *curs;
    cudaGetSymbolAddress((void**)&Z,    g_Z);
    cudaGetSymbolAddress((void**)&tau,  g_tau);
    cudaGetSymbolAddress((void**)&sd,   g_sd);
    cudaGetSymbolAddress((void**)&ss,   g_ss);
    cudaGetSymbolAddress((void**)&offd, g_offd);
    cudaGetSymbolAddress((void**)&offs, g_offs);
    cudaGetSymbolAddress((void**)&curd, g_curd);
    cudaGetSymbolAddress((void**)&curs, g_curs);

    const int SMEM128 = (64 * 68 + 64 * 132) * 4;   // 51200
    const int SMEM64  = (64 * 68 + 64 * 68) * 4;    // 34816
    cudaFuncSetAttribute(gemm_k<128, 0>, cudaFuncAttributeMaxDynamicSharedMemorySize, SMEM128);
    cudaFuncSetAttribute(gemm_k<128, 1>, cudaFuncAttributeMaxDynamicSharedMemorySize, SMEM128);
    cudaFuncSetAttribute(gemm_k<64, 2>,  cudaFuncAttributeMaxDynamicSharedMemorySize, SMEM64);

    const int gblocks = (NN + 63) / 64;   // 1563
    const int eblocks = (EE + 255) / 256;

    // ---- build CSR (layer-invariant) ----
    cudaMemsetAsync(curd, 0, NN * sizeof(int));
    cudaMemsetAsync(curs, 0, NN * sizeof(int));
    hist_k<<<eblocks, 256>>>(src, dst, curs, curd);
    scan_k<<<2, 1024>>>(curd, offd, curs, offs, NN);
    cudaMemcpyAsync(curd, offd, NN * sizeof(int), cudaMemcpyDeviceToDevice);
    cudaMemcpyAsync(curs, offs, NN * sizeof(int), cudaMemcpyDeviceToDevice);
    scatter_k<<<eblocks, 256>>>(src, dst, et, curd, curs, sd, ss);

    // ---- input projection: h0 = relu(x @ projW + projb) ----
    gemm_k<128, 0><<<gblocks, 128, SMEM128>>>(x, 128, 128, x, 128, NN, 128,
                                              projW, 128, nullptr,
                                              projb, nullptr, nullptr, L0);

    // ---- layer 1 ----
    passA_k<<<NN, 128>>>(L0, comp1, offd, sd, Z);
    passB_k<<<NN, 128>>>(L0, offs, ss, tau);
    gemm_k<128, 1><<<gblocks, 128, SMEM128>>>(Z, 512, 512, L0, 128, NN, 640,
                                              basis1, 512, root1,
                                              bias1, L0, tau, L1);

    // ---- layer 2 ----
    passA_k<<<NN, 128>>>(L1, comp2, offd, sd, Z);
    passB_k<<<NN, 128>>>(L1, offs, ss, tau);
    gemm_k<128, 1><<<gblocks, 128, SMEM128>>>(Z, 512, 512, L1, 128, NN, 640,
                                              basis2, 512, root2,
                                              bias2, L1, tau, L2);

    // ---- final: out = h2 @ outW + outb ----
    gemm_k<64, 2><<<gblocks, 128, SMEM64>>>(L2, 128, 128, L2, 128, NN, 128,
                                            outW, 128, nullptr,
                                            outb, nullptr, nullptr, o);
}

// round 6
// speedup vs baseline: 2.5410x; 1.0729x over previous
#include <cuda_runtime.h>
#include <cstdint>
#include <cstddef>

#define NN   100000
#define EE   1600000
#define DDIM 128
#define RREL 8
#define BBAS 4
#define OUTD 64

// ---------------- scratch (no cudaMalloc allowed) ----------------
__device__ float g_Z[(size_t)NN * 512];     // contracted aggregate [N, B*D]
__device__ float g_tau[(size_t)NN * DDIM];  // gate tau [N, D]
__device__ int   g_sd[EE];                  // edges sorted by dst: src | (q<<20)
__device__ int   g_ss[EE];                  // edges sorted by src: dst
__device__ int   g_offd[NN + 1];
__device__ int   g_offs[NN + 1];
__device__ int   g_curd[NN];
__device__ int   g_curs[NN];

// ---------------- sorting: histogram / scan / scatter ----------------
__global__ void hist_k(const int* __restrict__ src, const int* __restrict__ dst,
                       int* __restrict__ hs, int* __restrict__ hd) {
    int e = blockIdx.x * 256 + threadIdx.x;
    if (e < EE) {
        atomicAdd(&hd[dst[e]], 1);
        atomicAdd(&hs[src[e]], 1);
    }
}

__global__ void scan_k(const int* __restrict__ h0, int* __restrict__ o0,
                       const int* __restrict__ h1, int* __restrict__ o1, int n) {
    const int* hist = (blockIdx.x == 0) ? h0 : h1;
    int* off        = (blockIdx.x == 0) ? o0 : o1;
    __shared__ int buf[2][1024];
    __shared__ int carry;
    int t = threadIdx.x;
    if (t == 0) carry = 0;
    __syncthreads();
    for (int base = 0; base < n; base += 1024) {
        int v = (base + t < n) ? hist[base + t] : 0;
        buf[0][t] = v;
        __syncthreads();
        int pi = 0;
#pragma unroll
        for (int ofs = 1; ofs < 1024; ofs <<= 1) {
            int x = buf[pi][t];
            if (t >= ofs) x += buf[pi][t - ofs];
            buf[pi ^ 1][t] = x;
            pi ^= 1;
            __syncthreads();
        }
        int incl = buf[pi][t];
        if (base + t < n) off[base + t] = carry + incl - v;
        __syncthreads();
        if (t == 1023) carry += incl;
        __syncthreads();
    }
    if (t == 0) off[n] = carry;
}

__global__ void scatter_k(const int* __restrict__ src, const int* __restrict__ dst,
                          const int* __restrict__ et,
                          int* __restrict__ curd, int* __restrict__ curs,
                          int* __restrict__ sd, int* __restrict__ ss) {
    int e = blockIdx.x * 256 + threadIdx.x;
    if (e < EE) {
        int s = src[e], t = dst[e], q = et[e];
        int p = atomicAdd(&curd[t], 1);
        sd[p] = s | (q << 20);
        int p2 = atomicAdd(&curs[s], 1);
        ss[p2] = t;
    }
}

// ---------------- passA: per-dst segmented sum + comp contraction -> Z ----------------
__global__ __launch_bounds__(128)
void passA_k(const float* __restrict__ h, const float* __restrict__ comp,
             const int* __restrict__ offd, const int* __restrict__ sd,
             float* __restrict__ Z) {
    int t = blockIdx.x;
    int d = threadIdx.x;
    __shared__ float sacc[RREL * DDIM];
    __shared__ int   scnt[RREL];
    __shared__ float scomp[RREL * BBAS];
    __shared__ int   sed[128];
#pragma unroll
    for (int q = 0; q < RREL; ++q) sacc[q * DDIM + d] = 0.f;
    if (d < RREL) scnt[d] = 0;
    if (d < RREL * BBAS) scomp[d] = comp[d];
    __syncthreads();

    int e0 = offd[t], e1 = offd[t + 1];
    for (int base = e0; base < e1; base += 128) {
        int m = min(128, e1 - base);
        if (d < m) sed[d] = sd[base + d];
        __syncthreads();
        for (int i = 0; i < m; ++i) {
            int v = sed[i];
            int s = v & 0xFFFFF;
            int q = v >> 20;
            float hv = h[(size_t)s * DDIM + d];
            sacc[q * DDIM + d] += hv;
            if (d == 0) scnt[q]++;
        }
        __syncthreads();
    }

    float w[RREL];
#pragma unroll
    for (int q = 0; q < RREL; ++q)
        w[q] = 1.0f / fmaxf((float)scnt[q], 1.0f);

    float* zr = Z + (size_t)t * 512;
#pragma unroll
    for (int b = 0; b < BBAS; ++b) {
        float o = 0.f;
#pragma unroll
        for (int q = 0; q < RREL; ++q)
            o += scomp[q * BBAS + b] * w[q] * sacc[q * DDIM + d];
        zr[b * DDIM + d] = o;
    }
}

// ---------------- passB: per-src gate tau = tanh(mean |h_s - h_d|^2) ----------------
__global__ __launch_bounds__(128)
void passB_k(const float* __restrict__ h, const int* __restrict__ offs,
             const int* __restrict__ ss, float* __restrict__ tau) {
    int s = blockIdx.x;
    int d = threadIdx.x;
    int e0 = offs[s], e1 = offs[s + 1];
    float hs = h[(size_t)s * DDIM + d];
    float a0 = 0.f, a1 = 0.f, a2 = 0.f, a3 = 0.f;
    __shared__ int sed[128];
    for (int base = e0; base < e1; base += 128) {
        int m = min(128, e1 - base);
        if (d < m) sed[d] = ss[base + d];
        __syncthreads();
        int i = 0;
        for (; i + 3 < m; i += 4) {
            float v0 = h[(size_t)sed[i + 0] * DDIM + d];
            float v1 = h[(size_t)sed[i + 1] * DDIM + d];
            float v2 = h[(size_t)sed[i + 2] * DDIM + d];
            float v3 = h[(size_t)sed[i + 3] * DDIM + d];
            float d0 = hs - v0, d1 = hs - v1, d2 = hs - v2, d3 = hs - v3;
            a0 += d0 * d0; a1 += d1 * d1; a2 += d2 * d2; a3 += d3 * d3;
        }
        for (; i < m; ++i) {
            float v = h[(size_t)sed[i] * DDIM + d];
            float df = hs - v;
            a0 += df * df;
        }
        __syncthreads();
    }
    float acc = (a0 + a1) + (a2 + a3);
    float ig = 1.0f / fmaxf((float)(e1 - e0), 1.0f);
    tau[(size_t)s * DDIM + d] = tanhf(acc * ig);
}

// ---------------- 3xTF32 tensor-core GEMM ----------------
__device__ __forceinline__ void split_tf32(float x, uint32_t& hi, uint32_t& lo) {
    uint32_t xb = __float_as_uint(x) & 0xFFFFE000u;
    hi = xb;
    float l = x - __uint_as_float(xb);
    asm("cvt.rna.tf32.f32 %0, %1;" : "=r"(lo) : "f"(l));
}
__device__ __forceinline__ void mma8(float* d, const uint32_t* a, uint32_t b0, uint32_t b1) {
    asm volatile(
        "mma.sync.aligned.m16n8k8.row.col.f32.tf32.tf32.f32 "
        "{%0,%1,%2,%3}, {%4,%5,%6,%7}, {%8,%9}, {%0,%1,%2,%3};"
        : "+f"(d[0]), "+f"(d[1]), "+f"(d[2]), "+f"(d[3])
        : "r"(a[0]), "r"(a[1]), "r"(a[2]), "r"(a[3]), "r"(b0), "r"(b1));
}

// C[M,NC] = epi( A[M,K] @ [B1 (K1 rows); B2] ), A split at col K1A (A1/A2).
// BM=64, BK=32, 128 threads, warps 2x2: warp (wm,wn) -> rows wm*32+..32, cols wn*NC/2..
// EPI 0: relu(acc+bias)  EPI 1: hp + tau*(relu(acc+bias)-hp)  EPI 2: acc+bias
template <int NC, int EPI>
__global__ __launch_bounds__(128)
void gemm_mma(const float* __restrict__ A1, int lda1, int K1A,
              const float* __restrict__ A2, int lda2,
              int M, int K,
              const float* __restrict__ B1, int K1,
              const float* __restrict__ B2,
              const float* __restrict__ bias,
              const float* __restrict__ hprev,
              const float* __restrict__ tau,
              float* __restrict__ out) {
    constexpr int NCH = NC / 2;           // cols per warp
    constexpr int NT  = NCH / 8;          // n8 tiles per warp
    constexpr int BPAD = NC + 8;          // bank-conflict-free frag reads
    __shared__ float As[64][36];
    __shared__ float Bs[32][BPAD];

    const int tid  = threadIdx.x;
    const int lane = tid & 31;
    const int warp = tid >> 5;
    const int wm   = warp & 1;            // row half
    const int wn   = warp >> 1;           // col half
    const int g    = lane >> 2;
    const int tig  = lane & 3;
    const int row0 = blockIdx.x * 64;

    float acc[2][NT][4];
#pragma unroll
    for (int mt = 0; mt < 2; ++mt)
#pragma unroll
        for (int nt = 0; nt < NT; ++nt)
#pragma unroll
            for (int j = 0; j < 4; ++j) acc[mt][nt][j] = 0.f;

    const int nch = K >> 5;
    for (int c = 0; c < nch; ++c) {
        const int k0g = c << 5;
        // --- stage A: 64 x 32 floats (512 float4, 4/thread) ---
        const float* Ap; int lda;
        if (k0g < K1A) { Ap = A1 + k0g; lda = lda1; }
        else           { Ap = A2 + (k0g - K1A); lda = lda2; }
#pragma unroll
        for (int u = 0; u < 4; ++u) {
            int f = u * 128 + tid;
            int r = f >> 3;
            int q = f & 7;
            int grow = row0 + r;
            float4 v = make_float4(0.f, 0.f, 0.f, 0.f);
            if (grow < M) v = *(const float4*)(Ap + (size_t)grow * lda + q * 4);
            *(float4*)(&As[r][q * 4]) = v;
        }
        // --- stage B: 32 x NC floats ---
        const float* Bp = (k0g < K1) ? (B1 + (size_t)k0g * NC)
                                     : (B2 + (size_t)(k0g - K1) * NC);
#pragma unroll
        for (int u = 0; u < (32 * NC / 4) / 128; ++u) {
            int f = u * 128 + tid;
            int r = f / (NC / 4);
            int c4 = f % (NC / 4);
            *(float4*)(&Bs[r][c4 * 4]) = *(const float4*)(Bp + (size_t)r * NC + c4 * 4);
        }
        __syncthreads();

#pragma unroll
        for (int k8 = 0; k8 < 4; ++k8) {
            const int k0 = k8 * 8;
            // A fragments (hi/lo)
            uint32_t ah[2][4], al[2][4];
#pragma unroll
            for (int mt = 0; mt < 2; ++mt) {
                int rb = wm * 32 + mt * 16 + g;
                float a0 = As[rb][k0 + tig];
                float a1 = As[rb + 8][k0 + tig];
                float a2 = As[rb][k0 + tig + 4];
                float a3 = As[rb + 8][k0 + tig + 4];
                split_tf32(a0, ah[mt][0], al[mt][0]);
                split_tf32(a1, ah[mt][1], al[mt][1]);
                split_tf32(a2, ah[mt][2], al[mt][2]);
                split_tf32(a3, ah[mt][3], al[mt][3]);
            }
#pragma unroll
            for (int nt = 0; nt < NT; ++nt) {
                int cb = wn * NCH + nt * 8 + g;
                float b0 = Bs[k0 + tig][cb];
                float b1 = Bs[k0 + tig + 4][cb];
                uint32_t bh0, bl0, bh1, bl1;
                split_tf32(b0, bh0, bl0);
                split_tf32(b1, bh1, bl1);
#pragma unroll
                for (int mt = 0; mt < 2; ++mt) {
                    mma8(acc[mt][nt], ah[mt], bh0, bh1);
                    mma8(acc[mt][nt], al[mt], bh0, bh1);
                    mma8(acc[mt][nt], ah[mt], bl0, bl1);
                }
            }
        }
        __syncthreads();
    }

    // ---- epilogue ----
#pragma unroll
    for (int mt = 0; mt < 2; ++mt) {
#pragma unroll
        for (int nt = 0; nt < NT; ++nt) {
            int col = wn * NCH + nt * 8 + 2 * tig;
            int r0 = row0 + wm * 32 + mt * 16 + g;
#pragma unroll
            for (int half = 0; half < 2; ++half) {
                int row = r0 + half * 8;
                if (row >= M) continue;
                float c0 = acc[mt][nt][half * 2 + 0];
                float c1 = acc[mt][nt][half * 2 + 1];
                if (EPI == 0) {
                    c0 = fmaxf(c0 + bias[col], 0.f);
                    c1 = fmaxf(c1 + bias[col + 1], 0.f);
                } else if (EPI == 1) {
                    float hn0 = fmaxf(c0 + bias[col], 0.f);
                    float hn1 = fmaxf(c1 + bias[col + 1], 0.f);
                    float hp0 = hprev[(size_t)row * DDIM + col];
                    float hp1 = hprev[(size_t)row * DDIM + col + 1];
                    float t0 = tau[(size_t)row * DDIM + col];
                    float t1 = tau[(size_t)row * DDIM + col + 1];
                    c0 = hp0 + t0 * (hn0 - hp0);
                    c1 = hp1 + t1 * (hn1 - hp1);
                } else {
                    c0 += bias[col];
                    c1 += bias[col + 1];
                }
                *(float2*)(out + (size_t)row * NC + col) = make_float2(c0, c1);
            }
        }
    }
}

// ---------------- launch ----------------
extern "C" void kernel_launch(void* const* d_in, const int* in_sizes, int n_in,
                              void* d_out, int out_size) {
    (void)in_sizes; (void)n_in; (void)out_size;
    const float* x      = (const float*)d_in[0];
    const int*   src    = (const int*)d_in[1];
    const int*   dst    = (const int*)d_in[2];
    const int*   et     = (const int*)d_in[3];
    const float* projW  = (const float*)d_in[4];
    const float* projb  = (const float*)d_in[5];
    const float* basis1 = (const float*)d_in[6];
    const float* comp1  = (const float*)d_in[7];
    const float* root1  = (const float*)d_in[8];
    const float* bias1  = (const float*)d_in[9];
    const float* basis2 = (const float*)d_in[10];
    const float* comp2  = (const float*)d_in[11];
    const float* root2  = (const float*)d_in[12];
    const float* bias2  = (const float*)d_in[13];
    const float* outW   = (const float*)d_in[14];
    const float* outb   = (const float*)d_in[15];

    float* o  = (float*)d_out;
    float* L0 = o + (size_t)NN * OUTD;        // latents[0]
    float* L1 = L0 + (size_t)NN * DDIM;       // latents[1]
    float* L2 = L1 + (size_t)NN * DDIM;       // latents[2]

    float *Z, *tau;
    int *sd, *ss, *offd, *offs, *curd, *curs;
    cudaGetSymbolAddress((void**)&Z,    g_Z);
    cudaGetSymbolAddress((void**)&tau,  g_tau);
    cudaGetSymbolAddress((void**)&sd,   g_sd);
    cudaGetSymbolAddress((void**)&ss,   g_ss);
    cudaGetSymbolAddress((void**)&offd, g_offd);
    cudaGetSymbolAddress((void**)&offs, g_offs);
    cudaGetSymbolAddress((void**)&curd, g_curd);
    cudaGetSymbolAddress((void**)&curs, g_curs);

    const int gblocks = (NN + 63) / 64;   // 1563
    const int eblocks = (EE + 255) / 256;

    // ---- build CSR (layer-invariant) ----
    cudaMemsetAsync(curd, 0, NN * sizeof(int));
    cudaMemsetAsync(curs, 0, NN * sizeof(int));
    hist_k<<<eblocks, 256>>>(src, dst, curs, curd);
    scan_k<<<2, 1024>>>(curd, offd, curs, offs, NN);
    cudaMemcpyAsync(curd, offd, NN * sizeof(int), cudaMemcpyDeviceToDevice);
    cudaMemcpyAsync(curs, offs, NN * sizeof(int), cudaMemcpyDeviceToDevice);
    scatter_k<<<eblocks, 256>>>(src, dst, et, curd, curs, sd, ss);

    // ---- input projection: h0 = relu(x @ projW + projb) ----
    gemm_mma<128, 0><<<gblocks, 128>>>(x, 128, 128, x, 128, NN, 128,
                                       projW, 128, nullptr,
                                       projb, nullptr, nullptr, L0);

    // ---- layer 1 ----
    passA_k<<<NN, 128>>>(L0, comp1, offd, sd, Z);
    passB_k<<<NN, 128>>>(L0, offs, ss, tau);
    gemm_mma<128, 1><<<gblocks, 128>>>(Z, 512, 512, L0, 128, NN, 640,
                                       basis1, 512, root1,
                                       bias1, L0, tau, L1);

    // ---- layer 2 ----
    passA_k<<<NN, 128>>>(L1, comp2, offd, sd, Z);
    passB_k<<<NN, 128>>>(L1, offs, ss, tau);
    gemm_mma<128, 1><<<gblocks, 128>>>(Z, 512, 512, L1, 128, NN, 640,
                                       basis2, 512, root2,
                                       bias2, L1, tau, L2);

    // ---- final: out = h2 @ outW + outb ----
    gemm_mma<64, 2><<<gblocks, 128>>>(L2, 128, 128, L2, 128, NN, 128,
                                      outW, 128, nullptr,
                                      outb, nullptr, nullptr, o);
}

// round 7
// speedup vs baseline: 2.6649x; 1.0488x over previous
#include <cuda_runtime.h>
#include <cstdint>
#include <cstddef>

#define NN   100000
#define EE   1600000
#define DDIM 128
#define RREL 8
#define BBAS 4
#define OUTD 64

// ---------------- scratch (no cudaMalloc allowed) ----------------
__device__ float g_Z[(size_t)NN * 512];     // contracted aggregate [N, B*D]
__device__ float g_tau[(size_t)NN * DDIM];  // gate tau [N, D]
__device__ int   g_sd[EE];                  // edges sorted by dst: src | (q<<20)
__device__ int   g_ss[EE];                  // edges sorted by src: dst
__device__ int   g_offd[NN + 1];
__device__ int   g_offs[NN + 1];
__device__ int   g_curd[NN];
__device__ int   g_curs[NN];
// interleaved tf32 (hi,lo) weights: proj | basis1,root1 | basis2,root2 | outW
__device__ float g_Wi[2 * 188416];

// weight element offsets (un-interleaved space)
#define WOFF_PROJ 0
#define WOFF_B1   16384
#define WOFF_R1   81920
#define WOFF_B2   98304
#define WOFF_R2   163840
#define WOFF_OUT  180224

// ---------------- tf32 split helpers ----------------
__device__ __forceinline__ void split_tf32(float x, uint32_t& hi, uint32_t& lo) {
    uint32_t xb = __float_as_uint(x) & 0xFFFFE000u;
    hi = xb;
    float l = x - __uint_as_float(xb);
    asm("cvt.rna.tf32.f32 %0, %1;" : "=r"(lo) : "f"(l));
}
__device__ __forceinline__ void mma8(float* d, const uint32_t* a, uint32_t b0, uint32_t b1) {
    asm volatile(
        "mma.sync.aligned.m16n8k8.row.col.f32.tf32.tf32.f32 "
        "{%0,%1,%2,%3}, {%4,%5,%6,%7}, {%8,%9}, {%0,%1,%2,%3};"
        : "+f"(d[0]), "+f"(d[1]), "+f"(d[2]), "+f"(d[3])
        : "r"(a[0]), "r"(a[1]), "r"(a[2]), "r"(a[3]), "r"(b0), "r"(b1));
}

// ---------------- weight pre-split ----------------
__global__ void splitW_k(const float* __restrict__ W, float* __restrict__ Wi, int n) {
    int i = blockIdx.x * 256 + threadIdx.x;
    if (i < n) {
        uint32_t hi, lo;
        split_tf32(W[i], hi, lo);
        Wi[2 * i]     = __uint_as_float(hi);
        Wi[2 * i + 1] = __uint_as_float(lo);
    }
}

// ---------------- sorting: histogram / scan / scatter ----------------
__global__ void hist_k(const int* __restrict__ src, const int* __restrict__ dst,
                       int* __restrict__ hs, int* __restrict__ hd) {
    int e = blockIdx.x * 256 + threadIdx.x;
    if (e < EE) {
        atomicAdd(&hd[dst[e]], 1);
        atomicAdd(&hs[src[e]], 1);
    }
}

__global__ void scan_k(const int* __restrict__ h0, int* __restrict__ o0,
                       const int* __restrict__ h1, int* __restrict__ o1, int n) {
    const int* hist = (blockIdx.x == 0) ? h0 : h1;
    int* off        = (blockIdx.x == 0) ? o0 : o1;
    __shared__ int buf[2][1024];
    __shared__ int carry;
    int t = threadIdx.x;
    if (t == 0) carry = 0;
    __syncthreads();
    for (int base = 0; base < n; base += 1024) {
        int v = (base + t < n) ? hist[base + t] : 0;
        buf[0][t] = v;
        __syncthreads();
        int pi = 0;
#pragma unroll
        for (int ofs = 1; ofs < 1024; ofs <<= 1) {
            int x = buf[pi][t];
            if (t >= ofs) x += buf[pi][t - ofs];
            buf[pi ^ 1][t] = x;
            pi ^= 1;
            __syncthreads();
        }
        int incl = buf[pi][t];
        if (base + t < n) off[base + t] = carry + incl - v;
        __syncthreads();
        if (t == 1023) carry += incl;
        __syncthreads();
    }
    if (t == 0) off[n] = carry;
}

__global__ void scatter_k(const int* __restrict__ src, const int* __restrict__ dst,
                          const int* __restrict__ et,
                          int* __restrict__ curd, int* __restrict__ curs,
                          int* __restrict__ sd, int* __restrict__ ss) {
    int e = blockIdx.x * 256 + threadIdx.x;
    if (e < EE) {
        int s = src[e], t = dst[e], q = et[e];
        int p = atomicAdd(&curd[t], 1);
        sd[p] = s | (q << 20);
        int p2 = atomicAdd(&curs[s], 1);
        ss[p2] = t;
    }
}

// ---------------- passA: per-dst segmented sum + comp contraction -> Z ----------------
__global__ __launch_bounds__(128)
void passA_k(const float* __restrict__ h, const float* __restrict__ comp,
             const int* __restrict__ offd, const int* __restrict__ sd,
             float* __restrict__ Z) {
    int t = blockIdx.x;
    int d = threadIdx.x;
    __shared__ float sacc[RREL * DDIM];
    __shared__ int   scnt[RREL];
    __shared__ float scomp[RREL * BBAS];
    __shared__ int   sed[128];
#pragma unroll
    for (int q = 0; q < RREL; ++q) sacc[q * DDIM + d] = 0.f;
    if (d < RREL) scnt[d] = 0;
    if (d < RREL * BBAS) scomp[d] = comp[d];
    __syncthreads();

    int e0 = offd[t], e1 = offd[t + 1];
    for (int base = e0; base < e1; base += 128) {
        int m = min(128, e1 - base);
        if (d < m) sed[d] = sd[base + d];
        __syncthreads();
        int i = 0;
        for (; i + 3 < m; i += 4) {
            int v0 = sed[i], v1 = sed[i + 1], v2 = sed[i + 2], v3 = sed[i + 3];
            int s0 = v0 & 0xFFFFF, s1 = v1 & 0xFFFFF, s2 = v2 & 0xFFFFF, s3 = v3 & 0xFFFFF;
            int q0 = v0 >> 20, q1 = v1 >> 20, q2 = v2 >> 20, q3 = v3 >> 20;
            float h0 = h[(size_t)s0 * DDIM + d];
            float h1 = h[(size_t)s1 * DDIM + d];
            float h2 = h[(size_t)s2 * DDIM + d];
            float h3 = h[(size_t)s3 * DDIM + d];
            sacc[q0 * DDIM + d] += h0;
            sacc[q1 * DDIM + d] += h1;
            sacc[q2 * DDIM + d] += h2;
            sacc[q3 * DDIM + d] += h3;
            if (d == 0) { scnt[q0]++; scnt[q1]++; scnt[q2]++; scnt[q3]++; }
        }
        for (; i < m; ++i) {
            int v = sed[i];
            int s = v & 0xFFFFF;
            int q = v >> 20;
            sacc[q * DDIM + d] += h[(size_t)s * DDIM + d];
            if (d == 0) scnt[q]++;
        }
        __syncthreads();
    }

    float w[RREL];
#pragma unroll
    for (int q = 0; q < RREL; ++q)
        w[q] = 1.0f / fmaxf((float)scnt[q], 1.0f);

    float* zr = Z + (size_t)t * 512;
#pragma unroll
    for (int b = 0; b < BBAS; ++b) {
        float o = 0.f;
#pragma unroll
        for (int q = 0; q < RREL; ++q)
            o += scomp[q * BBAS + b] * w[q] * sacc[q * DDIM + d];
        zr[b * DDIM + d] = o;
    }
}

// ---------------- passB: per-src gate tau = tanh(mean |h_s - h_d|^2) ----------------
__global__ __launch_bounds__(128)
void passB_k(const float* __restrict__ h, const int* __restrict__ offs,
             const int* __restrict__ ss, float* __restrict__ tau) {
    int s = blockIdx.x;
    int d = threadIdx.x;
    int e0 = offs[s], e1 = offs[s + 1];
    float hs = h[(size_t)s * DDIM + d];
    float a0 = 0.f, a1 = 0.f, a2 = 0.f, a3 = 0.f;
    __shared__ int sed[128];
    for (int base = e0; base < e1; base += 128) {
        int m = min(128, e1 - base);
        if (d < m) sed[d] = ss[base + d];
        __syncthreads();
        int i = 0;
        for (; i + 3 < m; i += 4) {
            float v0 = h[(size_t)sed[i + 0] * DDIM + d];
            float v1 = h[(size_t)sed[i + 1] * DDIM + d];
            float v2 = h[(size_t)sed[i + 2] * DDIM + d];
            float v3 = h[(size_t)sed[i + 3] * DDIM + d];
            float d0 = hs - v0, d1 = hs - v1, d2 = hs - v2, d3 = hs - v3;
            a0 += d0 * d0; a1 += d1 * d1; a2 += d2 * d2; a3 += d3 * d3;
        }
        for (; i < m; ++i) {
            float v = h[(size_t)sed[i] * DDIM + d];
            float df = hs - v;
            a0 += df * df;
        }
        __syncthreads();
    }
    float acc = (a0 + a1) + (a2 + a3);
    float ig = 1.0f / fmaxf((float)(e1 - e0), 1.0f);
    tau[(size_t)s * DDIM + d] = tanhf(acc * ig);
}

// ---------------- 3xTF32 tensor-core GEMM, pre-split interleaved weights ----------------
// C[M,NC] = epi( A[M,K] @ W ), A split at col K1A (A1/A2); W = Wi interleaved (hi,lo) [K][2*NC]
// BM=64, BK=32, 128 threads, warps 2x2.
// EPI 0: relu(acc+bias)  EPI 1: hp + tau*(relu(acc+bias)-hp)  EPI 2: acc+bias
template <int NC, int EPI>
__global__ __launch_bounds__(128)
void gemm_mma(const float* __restrict__ A1, int lda1, int K1A,
              const float* __restrict__ A2, int lda2,
              int M, int K,
              const float* __restrict__ Wi,
              const float* __restrict__ bias,
              const float* __restrict__ hprev,
              const float* __restrict__ tau,
              float* __restrict__ out) {
    constexpr int NCH   = NC / 2;         // cols per warp
    constexpr int NT    = NCH / 8;        // n8 tiles per warp
    constexpr int BPAD2 = 2 * NC + 8;     // interleaved row stride (floats)
    __shared__ float As[64][36];
    __shared__ float Bs[32][BPAD2];

    const int tid  = threadIdx.x;
    const int lane = tid & 31;
    const int warp = tid >> 5;
    const int wm   = warp & 1;
    const int wn   = warp >> 1;
    const int g    = lane >> 2;
    const int tig  = lane & 3;
    const int row0 = blockIdx.x * 64;

    float acc[2][NT][4];
#pragma unroll
    for (int mt = 0; mt < 2; ++mt)
#pragma unroll
        for (int nt = 0; nt < NT; ++nt)
#pragma unroll
            for (int j = 0; j < 4; ++j) acc[mt][nt][j] = 0.f;

    const int nch = K >> 5;
    for (int c = 0; c < nch; ++c) {
        const int k0g = c << 5;
        // --- stage A: 64 x 32 floats ---
        const float* Ap; int lda;
        if (k0g < K1A) { Ap = A1 + k0g; lda = lda1; }
        else           { Ap = A2 + (k0g - K1A); lda = lda2; }
#pragma unroll
        for (int u = 0; u < 4; ++u) {
            int f = u * 128 + tid;
            int r = f >> 3;
            int q = f & 7;
            int grow = row0 + r;
            float4 v = make_float4(0.f, 0.f, 0.f, 0.f);
            if (grow < M) v = *(const float4*)(Ap + (size_t)grow * lda + q * 4);
            *(float4*)(&As[r][q * 4]) = v;
        }
        // --- stage B interleaved: 32 x 2NC floats, straight copy ---
        const float* Wp = Wi + (size_t)k0g * (2 * NC);
#pragma unroll
        for (int u = 0; u < NC / 8; ++u) {
            int f = u * 128 + tid;
            int r = f / (NC / 2);
            int c4 = f % (NC / 2);
            *(float4*)(&Bs[r][c4 * 4]) = *(const float4*)(Wp + (size_t)r * 2 * NC + c4 * 4);
        }
        __syncthreads();

#pragma unroll
        for (int k8 = 0; k8 < 4; ++k8) {
            const int k0 = k8 * 8;
            uint32_t ah[2][4], al[2][4];
#pragma unroll
            for (int mt = 0; mt < 2; ++mt) {
                int rb = wm * 32 + mt * 16 + g;
                split_tf32(As[rb][k0 + tig],          ah[mt][0], al[mt][0]);
                split_tf32(As[rb + 8][k0 + tig],      ah[mt][1], al[mt][1]);
                split_tf32(As[rb][k0 + tig + 4],      ah[mt][2], al[mt][2]);
                split_tf32(As[rb + 8][k0 + tig + 4],  ah[mt][3], al[mt][3]);
            }
#pragma unroll
            for (int nt = 0; nt < NT; ++nt) {
                int cb = wn * NCH + nt * 8 + g;
                float2 p0 = *(const float2*)(&Bs[k0 + tig][2 * cb]);
                float2 p1 = *(const float2*)(&Bs[k0 + tig + 4][2 * cb]);
                uint32_t bh0 = __float_as_uint(p0.x), bl0 = __float_as_uint(p0.y);
                uint32_t bh1 = __float_as_uint(p1.x), bl1 = __float_as_uint(p1.y);
#pragma unroll
                for (int mt = 0; mt < 2; ++mt) {
                    mma8(acc[mt][nt], ah[mt], bh0, bh1);
                    mma8(acc[mt][nt], al[mt], bh0, bh1);
                    mma8(acc[mt][nt], ah[mt], bl0, bl1);
                }
            }
        }
        __syncthreads();
    }

    // ---- epilogue ----
#pragma unroll
    for (int mt = 0; mt < 2; ++mt) {
#pragma unroll
        for (int nt = 0; nt < NT; ++nt) {
            int col = wn * NCH + nt * 8 + 2 * tig;
            int r0 = row0 + wm * 32 + mt * 16 + g;
#pragma unroll
            for (int half = 0; half < 2; ++half) {
                int row = r0 + half * 8;
                if (row >= M) continue;
                float c0 = acc[mt][nt][half * 2 + 0];
                float c1 = acc[mt][nt][half * 2 + 1];
                if (EPI == 0) {
                    c0 = fmaxf(c0 + bias[col], 0.f);
                    c1 = fmaxf(c1 + bias[col + 1], 0.f);
                } else if (EPI == 1) {
                    float hn0 = fmaxf(c0 + bias[col], 0.f);
                    float hn1 = fmaxf(c1 + bias[col + 1], 0.f);
                    float hp0 = hprev[(size_t)row * DDIM + col];
                    float hp1 = hprev[(size_t)row * DDIM + col + 1];
                    float t0 = tau[(size_t)row * DDIM + col];
                    float t1 = tau[(size_t)row * DDIM + col + 1];
                    c0 = hp0 + t0 * (hn0 - hp0);
                    c1 = hp1 + t1 * (hn1 - hp1);
                } else {
                    c0 += bias[col];
                    c1 += bias[col + 1];
                }
                *(float2*)(out + (size_t)row * NC + col) = make_float2(c0, c1);
            }
        }
    }
}

// ---------------- launch ----------------
extern "C" void kernel_launch(void* const* d_in, const int* in_sizes, int n_in,
                              void* d_out, int out_size) {
    (void)in_sizes; (void)n_in; (void)out_size;
    const float* x      = (const float*)d_in[0];
    const int*   src    = (const int*)d_in[1];
    const int*   dst    = (const int*)d_in[2];
    const int*   et     = (const int*)d_in[3];
    const float* projW  = (const float*)d_in[4];
    const float* projb  = (const float*)d_in[5];
    const float* basis1 = (const float*)d_in[6];
    const float* comp1  = (const float*)d_in[7];
    const float* root1  = (const float*)d_in[8];
    const float* bias1  = (const float*)d_in[9];
    const float* basis2 = (const float*)d_in[10];
    const float* comp2  = (const float*)d_in[11];
    const float* root2  = (const float*)d_in[12];
    const float* bias2  = (const float*)d_in[13];
    const float* outW   = (const float*)d_in[14];
    const float* outb   = (const float*)d_in[15];

    float* o  = (float*)d_out;
    float* L0 = o + (size_t)NN * OUTD;        // latents[0]
    float* L1 = L0 + (size_t)NN * DDIM;       // latents[1]
    float* L2 = L1 + (size_t)NN * DDIM;       // latents[2]

    float *Z, *tau, *Wi;
    int *sd, *ss, *offd, *offs, *curd, *curs;
    cudaGetSymbolAddress((void**)&Z,    g_Z);
    cudaGetSymbolAddress((void**)&tau,  g_tau);
    cudaGetSymbolAddress((void**)&Wi,   g_Wi);
    cudaGetSymbolAddress((void**)&sd,   g_sd);
    cudaGetSymbolAddress((void**)&ss,   g_ss);
    cudaGetSymbolAddress((void**)&offd, g_offd);
    cudaGetSymbolAddress((void**)&offs, g_offs);
    cudaGetSymbolAddress((void**)&curd, g_curd);
    cudaGetSymbolAddress((void**)&curs, g_curs);

    const int gblocks = (NN + 63) / 64;   // 1563
    const int eblocks = (EE + 255) / 256;

    // ---- pre-split weights (layer-invariant) ----
    splitW_k<<<(16384 + 255) / 256, 256>>>(projW,  Wi + 2 * WOFF_PROJ, 16384);
    splitW_k<<<(65536 + 255) / 256, 256>>>(basis1, Wi + 2 * WOFF_B1,   65536);
    splitW_k<<<(16384 + 255) / 256, 256>>>(root1,  Wi + 2 * WOFF_R1,   16384);
    splitW_k<<<(65536 + 255) / 256, 256>>>(basis2, Wi + 2 * WOFF_B2,   65536);
    splitW_k<<<(16384 + 255) / 256, 256>>>(root2,  Wi + 2 * WOFF_R2,   16384);
    splitW_k<<<(8192  + 255) / 256, 256>>>(outW,   Wi + 2 * WOFF_OUT,  8192);

    // ---- build CSR (layer-invariant) ----
    cudaMemsetAsync(curd, 0, NN * sizeof(int));
    cudaMemsetAsync(curs, 0, NN * sizeof(int));
    hist_k<<<eblocks, 256>>>(src, dst, curs, curd);
    scan_k<<<2, 1024>>>(curd, offd, curs, offs, NN);
    cudaMemcpyAsync(curd, offd, NN * sizeof(int), cudaMemcpyDeviceToDevice);
    cudaMemcpyAsync(curs, offs, NN * sizeof(int), cudaMemcpyDeviceToDevice);
    scatter_k<<<eblocks, 256>>>(src, dst, et, curd, curs, sd, ss);

    // ---- input projection: h0 = relu(x @ projW + projb) ----
    gemm_mma<128, 0><<<gblocks, 128>>>(x, 128, 128, x, 128, NN, 128,
                                       Wi + 2 * WOFF_PROJ,
                                       projb, nullptr, nullptr, L0);

    // ---- layer 1 ----
    passA_k<<<NN, 128>>>(L0, comp1, offd, sd, Z);
    passB_k<<<NN, 128>>>(L0, offs, ss, tau);
    gemm_mma<128, 1><<<gblocks, 128>>>(Z, 512, 512, L0, 128, NN, 640,
                                       Wi + 2 * WOFF_B1,
                                       bias1, L0, tau, L1);

    // ---- layer 2 ----
    passA_k<<<NN, 128>>>(L1, comp2, offd, sd, Z);
    passB_k<<<NN, 128>>>(L1, offs, ss, tau);
    gemm_mma<128, 1><<<gblocks, 128>>>(Z, 512, 512, L1, 128, NN, 640,
                                       Wi + 2 * WOFF_B2,
                                       bias2, L1, tau, L2);

    // ---- final: out = h2 @ outW + outb ----
    gemm_mma<64, 2><<<gblocks, 128>>>(L2, 128, 128, L2, 128, NN, 128,
                                      Wi + 2 * WOFF_OUT,
                                      outb, nullptr, nullptr, o);
}

// round 8
// speedup vs baseline: 2.7756x; 1.0415x over previous
#include <cuda_runtime.h>
#include <cstdint>
#include <cstddef>

#define NN   100000
#define EE   1600000
#define DDIM 128
#define RREL 8
#define BBAS 4
#define OUTD 64

// ---------------- scratch (no cudaMalloc allowed) ----------------
__device__ float g_Z[(size_t)NN * 512];     // contracted aggregate [N, B*D]
__device__ float g_tau[(size_t)NN * DDIM];  // gate tau [N, D]
__device__ int   g_sd[EE];                  // edges sorted by dst: src | (q<<20)
__device__ int   g_ss[EE];                  // edges sorted by src: dst
__device__ int   g_offd[NN + 1];
__device__ int   g_offs[NN + 1];
__device__ int   g_curd[NN];
__device__ int   g_curs[NN];
// interleaved tf32 (hi,lo) weights: proj | basis1,root1 | basis2,root2 | outW
__device__ float g_Wi[2 * 188416];

#define WOFF_PROJ 0
#define WOFF_B1   16384
#define WOFF_R1   81920
#define WOFF_B2   98304
#define WOFF_R2   163840
#define WOFF_OUT  180224

// ---------------- tf32 split helpers ----------------
__device__ __forceinline__ void split_tf32(float x, uint32_t& hi, uint32_t& lo) {
    uint32_t xb = __float_as_uint(x) & 0xFFFFE000u;
    hi = xb;
    float l = x - __uint_as_float(xb);
    asm("cvt.rna.tf32.f32 %0, %1;" : "=r"(lo) : "f"(l));
}
__device__ __forceinline__ void mma8(float* d, const uint32_t* a, uint32_t b0, uint32_t b1) {
    asm volatile(
        "mma.sync.aligned.m16n8k8.row.col.f32.tf32.tf32.f32 "
        "{%0,%1,%2,%3}, {%4,%5,%6,%7}, {%8,%9}, {%0,%1,%2,%3};"
        : "+f"(d[0]), "+f"(d[1]), "+f"(d[2]), "+f"(d[3])
        : "r"(a[0]), "r"(a[1]), "r"(a[2]), "r"(a[3]), "r"(b0), "r"(b1));
}

// ---------------- cp.async helpers ----------------
__device__ __forceinline__ void cp16(uint32_t dst, const void* src, int srcsz) {
    asm volatile("cp.async.ca.shared.global [%0], [%1], 16, %2;"
                 :: "r"(dst), "l"(src), "r"(srcsz));
}
__device__ __forceinline__ void cp_commit() {
    asm volatile("cp.async.commit_group;");
}
template <int N>
__device__ __forceinline__ void cp_wait() {
    asm volatile("cp.async.wait_group %0;" :: "n"(N));
}

// ---------------- weight pre-split ----------------
__global__ void splitW_k(const float* __restrict__ W, float* __restrict__ Wi, int n) {
    int i = blockIdx.x * 256 + threadIdx.x;
    if (i < n) {
        uint32_t hi, lo;
        split_tf32(W[i], hi, lo);
        Wi[2 * i]     = __uint_as_float(hi);
        Wi[2 * i + 1] = __uint_as_float(lo);
    }
}

// ---------------- sorting: histogram / scan / scatter ----------------
__global__ void hist_k(const int* __restrict__ src, const int* __restrict__ dst,
                       int* __restrict__ hs, int* __restrict__ hd) {
    int e = blockIdx.x * 256 + threadIdx.x;
    if (e < EE) {
        atomicAdd(&hd[dst[e]], 1);
        atomicAdd(&hs[src[e]], 1);
    }
}

__global__ void scan_k(const int* __restrict__ h0, int* __restrict__ o0,
                       const int* __restrict__ h1, int* __restrict__ o1, int n) {
    const int* hist = (blockIdx.x == 0) ? h0 : h1;
    int* off        = (blockIdx.x == 0) ? o0 : o1;
    __shared__ int buf[2][1024];
    __shared__ int carry;
    int t = threadIdx.x;
    if (t == 0) carry = 0;
    __syncthreads();
    for (int base = 0; base < n; base += 1024) {
        int v = (base + t < n) ? hist[base + t] : 0;
        buf[0][t] = v;
        __syncthreads();
        int pi = 0;
#pragma unroll
        for (int ofs = 1; ofs < 1024; ofs <<= 1) {
            int x = buf[pi][t];
            if (t >= ofs) x += buf[pi][t - ofs];
            buf[pi ^ 1][t] = x;
            pi ^= 1;
            __syncthreads();
        }
        int incl = buf[pi][t];
        if (base + t < n) off[base + t] = carry + incl - v;
        __syncthreads();
        if (t == 1023) carry += incl;
        __syncthreads();
    }
    if (t == 0) off[n] = carry;
}

__global__ void scatter_k(const int* __restrict__ src, const int* __restrict__ dst,
                          const int* __restrict__ et,
                          int* __restrict__ curd, int* __restrict__ curs,
                          int* __restrict__ sd, int* __restrict__ ss) {
    int e = blockIdx.x * 256 + threadIdx.x;
    if (e < EE) {
        int s = src[e], t = dst[e], q = et[e];
        int p = atomicAdd(&curd[t], 1);
        sd[p] = s | (q << 20);
        int p2 = atomicAdd(&curs[s], 1);
        ss[p2] = t;
    }
}

// ---------------- passA: per-dst segmented sum + comp contraction -> Z ----------------
__global__ __launch_bounds__(128)
void passA_k(const float* __restrict__ h, const float* __restrict__ comp,
             const int* __restrict__ offd, const int* __restrict__ sd,
             float* __restrict__ Z) {
    int t = blockIdx.x;
    int d = threadIdx.x;
    __shared__ float sacc[RREL * DDIM];
    __shared__ int   scnt[RREL];
    __shared__ float scomp[RREL * BBAS];
    __shared__ int   sed[128];
#pragma unroll
    for (int q = 0; q < RREL; ++q) sacc[q * DDIM + d] = 0.f;
    if (d < RREL) scnt[d] = 0;
    if (d < RREL * BBAS) scomp[d] = comp[d];
    __syncthreads();

    int e0 = offd[t], e1 = offd[t + 1];
    for (int base = e0; base < e1; base += 128) {
        int m = min(128, e1 - base);
        if (d < m) sed[d] = sd[base + d];
        __syncthreads();
        int i = 0;
        for (; i + 3 < m; i += 4) {
            int v0 = sed[i], v1 = sed[i + 1], v2 = sed[i + 2], v3 = sed[i + 3];
            int s0 = v0 & 0xFFFFF, s1 = v1 & 0xFFFFF, s2 = v2 & 0xFFFFF, s3 = v3 & 0xFFFFF;
            int q0 = v0 >> 20, q1 = v1 >> 20, q2 = v2 >> 20, q3 = v3 >> 20;
            float h0 = h[(size_t)s0 * DDIM + d];
            float h1 = h[(size_t)s1 * DDIM + d];
            float h2 = h[(size_t)s2 * DDIM + d];
            float h3 = h[(size_t)s3 * DDIM + d];
            sacc[q0 * DDIM + d] += h0;
            sacc[q1 * DDIM + d] += h1;
            sacc[q2 * DDIM + d] += h2;
            sacc[q3 * DDIM + d] += h3;
            if (d == 0) { scnt[q0]++; scnt[q1]++; scnt[q2]++; scnt[q3]++; }
        }
        for (; i < m; ++i) {
            int v = sed[i];
            int s = v & 0xFFFFF;
            int q = v >> 20;
            sacc[q * DDIM + d] += h[(size_t)s * DDIM + d];
            if (d == 0) scnt[q]++;
        }
        __syncthreads();
    }

    float w[RREL];
#pragma unroll
    for (int q = 0; q < RREL; ++q)
        w[q] = 1.0f / fmaxf((float)scnt[q], 1.0f);

    float* zr = Z + (size_t)t * 512;
#pragma unroll
    for (int b = 0; b < BBAS; ++b) {
        float o = 0.f;
#pragma unroll
        for (int q = 0; q < RREL; ++q)
            o += scomp[q * BBAS + b] * w[q] * sacc[q * DDIM + d];
        zr[b * DDIM + d] = o;
    }
}

// ---------------- passB: per-src gate tau = tanh(mean |h_s - h_d|^2) ----------------
__global__ __launch_bounds__(128)
void passB_k(const float* __restrict__ h, const int* __restrict__ offs,
             const int* __restrict__ ss, float* __restrict__ tau) {
    int s = blockIdx.x;
    int d = threadIdx.x;
    int e0 = offs[s], e1 = offs[s + 1];
    float hs = h[(size_t)s * DDIM + d];
    float a0 = 0.f, a1 = 0.f, a2 = 0.f, a3 = 0.f;
    __shared__ int sed[128];
    for (int base = e0; base < e1; base += 128) {
        int m = min(128, e1 - base);
        if (d < m) sed[d] = ss[base + d];
        __syncthreads();
        int i = 0;
        for (; i + 3 < m; i += 4) {
            float v0 = h[(size_t)sed[i + 0] * DDIM + d];
            float v1 = h[(size_t)sed[i + 1] * DDIM + d];
            float v2 = h[(size_t)sed[i + 2] * DDIM + d];
            float v3 = h[(size_t)sed[i + 3] * DDIM + d];
            float d0 = hs - v0, d1 = hs - v1, d2 = hs - v2, d3 = hs - v3;
            a0 += d0 * d0; a1 += d1 * d1; a2 += d2 * d2; a3 += d3 * d3;
        }
        for (; i < m; ++i) {
            float v = h[(size_t)sed[i] * DDIM + d];
            float df = hs - v;
            a0 += df * df;
        }
        __syncthreads();
    }
    float acc = (a0 + a1) + (a2 + a3);
    float ig = 1.0f / fmaxf((float)(e1 - e0), 1.0f);
    tau[(size_t)s * DDIM + d] = tanhf(acc * ig);
}

// ---------------- 3xTF32 MMA GEMM, cp.async double-buffered, BK=16 ----------------
// C[M,NC] = epi( A[M,K] @ W ), A split at col K1A (A1/A2); W interleaved (hi,lo) [K][2*NC]
// BM=64, BK=16, 128 threads, warps 2x2.
template <int NC, int EPI>
__global__ __launch_bounds__(128)
void gemm_mma(const float* __restrict__ A1, int lda1, int K1A,
              const float* __restrict__ A2, int lda2,
              int M, int K,
              const float* __restrict__ Wi,
              const float* __restrict__ bias,
              const float* __restrict__ hprev,
              const float* __restrict__ tau,
              float* __restrict__ out) {
    constexpr int NCH   = NC / 2;         // cols per warp
    constexpr int NT    = NCH / 8;        // n8 tiles per warp
    constexpr int APAD  = 20;             // 16 + 4
    constexpr int BPAD2 = 2 * NC + 8;     // interleaved row stride
    __shared__ float As[2][64][APAD];
    __shared__ float Bs[2][16][BPAD2];

    const int tid  = threadIdx.x;
    const int lane = tid & 31;
    const int warp = tid >> 5;
    const int wm   = warp & 1;
    const int wn   = warp >> 1;
    const int g    = lane >> 2;
    const int tig  = lane & 3;
    const int row0 = blockIdx.x * 64;

    float acc[2][NT][4];
#pragma unroll
    for (int mt = 0; mt < 2; ++mt)
#pragma unroll
        for (int nt = 0; nt < NT; ++nt)
#pragma unroll
            for (int j = 0; j < 4; ++j) acc[mt][nt][j] = 0.f;

    const int nch = K >> 4;

    auto load_chunk = [&](int c, int buf) {
        const int k0g = c << 4;
        const float* Ap; int lda;
        if (k0g < K1A) { Ap = A1 + k0g; lda = lda1; }
        else           { Ap = A2 + (k0g - K1A); lda = lda2; }
        // A: 64 rows x 4 float4 = 256 slots, 2/thread
#pragma unroll
        for (int u = 0; u < 2; ++u) {
            int f = u * 128 + tid;
            int r = f >> 2;
            int q = f & 3;
            int grow = row0 + r;
            uint32_t dsts = (uint32_t)__cvta_generic_to_shared(&As[buf][r][q * 4]);
            const float* srcp = Ap + (size_t)(grow < M ? grow : 0) * lda + q * 4;
            cp16(dsts, srcp, grow < M ? 16 : 0);
        }
        // B: 16 rows x (NC/2) float4 = 16*NC/2 slots
        const float* Wp = Wi + (size_t)k0g * (2 * NC);
#pragma unroll
        for (int u = 0; u < NC / 16; ++u) {
            int f = u * 128 + tid;
            int r = f / (NC / 2);
            int c4 = f % (NC / 2);
            uint32_t dsts = (uint32_t)__cvta_generic_to_shared(&Bs[buf][r][c4 * 4]);
            cp16(dsts, Wp + (size_t)r * 2 * NC + c4 * 4, 16);
        }
    };

    load_chunk(0, 0);
    cp_commit();

    for (int c = 0; c < nch; ++c) {
        const int buf = c & 1;
        if (c + 1 < nch) {
            load_chunk(c + 1, buf ^ 1);
            cp_commit();
            cp_wait<1>();
        } else {
            cp_wait<0>();
        }
        __syncthreads();

#pragma unroll
        for (int k8 = 0; k8 < 2; ++k8) {
            const int k0 = k8 * 8;
            uint32_t ah[2][4], al[2][4];
#pragma unroll
            for (int mt = 0; mt < 2; ++mt) {
                int rb = wm * 32 + mt * 16 + g;
                split_tf32(As[buf][rb][k0 + tig],          ah[mt][0], al[mt][0]);
                split_tf32(As[buf][rb + 8][k0 + tig],      ah[mt][1], al[mt][1]);
                split_tf32(As[buf][rb][k0 + tig + 4],      ah[mt][2], al[mt][2]);
                split_tf32(As[buf][rb + 8][k0 + tig + 4],  ah[mt][3], al[mt][3]);
            }
#pragma unroll
            for (int nt = 0; nt < NT; ++nt) {
                int cb = wn * NCH + nt * 8 + g;
                float2 p0 = *(const float2*)(&Bs[buf][k0 + tig][2 * cb]);
                float2 p1 = *(const float2*)(&Bs[buf][k0 + tig + 4][2 * cb]);
                uint32_t bh0 = __float_as_uint(p0.x), bl0 = __float_as_uint(p0.y);
                uint32_t bh1 = __float_as_uint(p1.x), bl1 = __float_as_uint(p1.y);
#pragma unroll
                for (int mt = 0; mt < 2; ++mt) {
                    mma8(acc[mt][nt], ah[mt], bh0, bh1);
                    mma8(acc[mt][nt], al[mt], bh0, bh1);
                    mma8(acc[mt][nt], ah[mt], bl0, bl1);
                }
            }
        }
        __syncthreads();
    }

    // ---- epilogue ----
#pragma unroll
    for (int mt = 0; mt < 2; ++mt) {
#pragma unroll
        for (int nt = 0; nt < NT; ++nt) {
            int col = wn * NCH + nt * 8 + 2 * tig;
            int r0 = row0 + wm * 32 + mt * 16 + g;
#pragma unroll
            for (int half = 0; half < 2; ++half) {
                int row = r0 + half * 8;
                if (row >= M) continue;
                float c0 = acc[mt][nt][half * 2 + 0];
                float c1 = acc[mt][nt][half * 2 + 1];
                if (EPI == 0) {
                    c0 = fmaxf(c0 + bias[col], 0.f);
                    c1 = fmaxf(c1 + bias[col + 1], 0.f);
                } else if (EPI == 1) {
                    float hn0 = fmaxf(c0 + bias[col], 0.f);
                    float hn1 = fmaxf(c1 + bias[col + 1], 0.f);
                    float hp0 = hprev[(size_t)row * DDIM + col];
                    float hp1 = hprev[(size_t)row * DDIM + col + 1];
                    float t0 = tau[(size_t)row * DDIM + col];
                    float t1 = tau[(size_t)row * DDIM + col + 1];
                    c0 = hp0 + t0 * (hn0 - hp0);
                    c1 = hp1 + t1 * (hn1 - hp1);
                } else {
                    c0 += bias[col];
                    c1 += bias[col + 1];
                }
                *(float2*)(out + (size_t)row * NC + col) = make_float2(c0, c1);
            }
        }
    }
}

// ---------------- launch ----------------
extern "C" void kernel_launch(void* const* d_in, const int* in_sizes, int n_in,
                              void* d_out, int out_size) {
    (void)in_sizes; (void)n_in; (void)out_size;
    const float* x      = (const float*)d_in[0];
    const int*   src    = (const int*)d_in[1];
    const int*   dst    = (const int*)d_in[2];
    const int*   et     = (const int*)d_in[3];
    const float* projW  = (const float*)d_in[4];
    const float* projb  = (const float*)d_in[5];
    const float* basis1 = (const float*)d_in[6];
    const float* comp1  = (const float*)d_in[7];
    const float* root1  = (const float*)d_in[8];
    const float* bias1  = (const float*)d_in[9];
    const float* basis2 = (const float*)d_in[10];
    const float* comp2  = (const float*)d_in[11];
    const float* root2  = (const float*)d_in[12];
    const float* bias2  = (const float*)d_in[13];
    const float* outW   = (const float*)d_in[14];
    const float* outb   = (const float*)d_in[15];

    float* o  = (float*)d_out;
    float* L0 = o + (size_t)NN * OUTD;        // latents[0]
    float* L1 = L0 + (size_t)NN * DDIM;       // latents[1]
    float* L2 = L1 + (size_t)NN * DDIM;       // latents[2]

    float *Z, *tau, *Wi;
    int *sd, *ss, *offd, *offs, *curd, *curs;
    cudaGetSymbolAddress((void**)&Z,    g_Z);
    cudaGetSymbolAddress((void**)&tau,  g_tau);
    cudaGetSymbolAddress((void**)&Wi,   g_Wi);
    cudaGetSymbolAddress((void**)&sd,   g_sd);
    cudaGetSymbolAddress((void**)&ss,   g_ss);
    cudaGetSymbolAddress((void**)&offd, g_offd);
    cudaGetSymbolAddress((void**)&offs, g_offs);
    cudaGetSymbolAddress((void**)&curd, g_curd);
    cudaGetSymbolAddress((void**)&curs, g_curs);

    const int gblocks = (NN + 63) / 64;   // 1563
    const int eblocks = (EE + 255) / 256;

    // ---- pre-split weights (layer-invariant) ----
    splitW_k<<<(16384 + 255) / 256, 256>>>(projW,  Wi + 2 * WOFF_PROJ, 16384);
    splitW_k<<<(65536 + 255) / 256, 256>>>(basis1, Wi + 2 * WOFF_B1,   65536);
    splitW_k<<<(16384 + 255) / 256, 256>>>(root1,  Wi + 2 * WOFF_R1,   16384);
    splitW_k<<<(65536 + 255) / 256, 256>>>(basis2, Wi + 2 * WOFF_B2,   65536);
    splitW_k<<<(16384 + 255) / 256, 256>>>(root2,  Wi + 2 * WOFF_R2,   16384);
    splitW_k<<<(8192  + 255) / 256, 256>>>(outW,   Wi + 2 * WOFF_OUT,  8192);

    // ---- build CSR (layer-invariant) ----
    cudaMemsetAsync(curd, 0, NN * sizeof(int));
    cudaMemsetAsync(curs, 0, NN * sizeof(int));
    hist_k<<<eblocks, 256>>>(src, dst, curs, curd);
    scan_k<<<2, 1024>>>(curd, offd, curs, offs, NN);
    cudaMemcpyAsync(curd, offd, NN * sizeof(int), cudaMemcpyDeviceToDevice);
    cudaMemcpyAsync(curs, offs, NN * sizeof(int), cudaMemcpyDeviceToDevice);
    scatter_k<<<eblocks, 256>>>(src, dst, et, curd, curs, sd, ss);

    // ---- input projection: h0 = relu(x @ projW + projb) ----
    gemm_mma<128, 0><<<gblocks, 128>>>(x, 128, 128, x, 128, NN, 128,
                                       Wi + 2 * WOFF_PROJ,
                                       projb, nullptr, nullptr, L0);

    // ---- layer 1 ----
    passA_k<<<NN, 128>>>(L0, comp1, offd, sd, Z);
    passB_k<<<NN, 128>>>(L0, offs, ss, tau);
    gemm_mma<128, 1><<<gblocks, 128>>>(Z, 512, 512, L0, 128, NN, 640,
                                       Wi + 2 * WOFF_B1,
                                       bias1, L0, tau, L1);

    // ---- layer 2 ----
    passA_k<<<NN, 128>>>(L1, comp2, offd, sd, Z);
    passB_k<<<NN, 128>>>(L1, offs, ss, tau);
    gemm_mma<128, 1><<<gblocks, 128>>>(Z, 512, 512, L1, 128, NN, 640,
                                       Wi + 2 * WOFF_B2,
                                       bias2, L1, tau, L2);

    // ---- final: out = h2 @ outW + outb ----
    gemm_mma<64, 2><<<gblocks, 128>>>(L2, 128, 128, L2, 128, NN, 128,
                                      Wi + 2 * WOFF_OUT,
                                      outb, nullptr, nullptr, o);
}